// round 10
// baseline (speedup 1.0000x reference)
#include <cuda_runtime.h>
#include <cuda_bf16.h>
#include <mma.h>
#include <math.h>
#include <stdint.h>

using namespace nvcuda;

#define BB 8
#define NN 1024
#define DD 256
#define EE 32768
#define DFF 1024
#define MM (BB*NN)          // 8192 rows

// ---------------- scratch (static device globals; no allocation) ----------------
__device__ float g_qkv[MM*768];            // fused q|k|v (fp32)
__device__ float g_ao [MM*DD];
__device__ float g_op [MM*DD];
__device__ float g_x  [MM*DD];
__device__ float g_f  [MM*DD];
__device__ float g_h  [MM*DFF];
__device__ float g_proj[BB*EE];
__device__ int   g_lastE[BB*NN*NN];
__device__ float g_bqkv[768];
// fp32 transposed weights [N,K] K-major
__device__ float g_wqkvT[768*DD];
__device__ float g_woT [DD*DD];
__device__ float g_w1T [DFF*DD];
__device__ float g_w2T [DD*DFF];

// ==================== helpers ====================
__device__ __forceinline__ uint32_t smem_u32(const void* p) {
    uint32_t a;
    asm("{ .reg .u64 t; cvta.to.shared.u64 t, %1; cvt.u32.u64 %0, t; }" : "=r"(a) : "l"(p));
    return a;
}
__device__ __forceinline__ void cpa16(uint32_t dst, const void* src) {
    asm volatile("cp.async.cg.shared.global [%0], [%1], 16;" :: "r"(dst), "l"(src));
}
#define CP_COMMIT asm volatile("cp.async.commit_group;" ::: "memory")
#define CP_WAIT1  asm volatile("cp.async.wait_group 1;" ::: "memory")
#define CP_WAIT0  asm volatile("cp.async.wait_group 0;" ::: "memory")

// ==================== small kernels ====================
__global__ void init_lastE_kernel() {
    size_t idx = (size_t)blockIdx.x * blockDim.x + threadIdx.x;
    reinterpret_cast<int4*>(g_lastE)[idx] = make_int4(-1, -1, -1, -1);
}

// edge bias projection + adjacency scatter (fused)
__global__ void edge_kernel(const float* __restrict__ ea,
                            const float* __restrict__ ew,
                            const float* __restrict__ ebv,
                            const int* __restrict__ eidx) {
    int idx = blockIdx.x * blockDim.x + threadIdx.x;
    if (idx >= BB * EE) return;
    const float4* p = reinterpret_cast<const float4*>(ea + (size_t)idx * 16);
    const float4* w = reinterpret_cast<const float4*>(ew);
    float s = ebv[0];
    #pragma unroll
    for (int t = 0; t < 4; t++) {
        float4 a = p[t], b = w[t];
        s += a.x * b.x + a.y * b.y + a.z * b.z + a.w * b.w;
    }
    g_proj[idx] = s;
    int b = idx >> 15, e = idx & (EE - 1);
    int si = eidx[(b * 2 + 0) * EE + e];
    int di = eidx[(b * 2 + 1) * EE + e];
    if ((unsigned)si < (unsigned)NN && (unsigned)di < (unsigned)NN)
        atomicMax(&g_lastE[((size_t)(b * NN + si)) * NN + di], e);
}

// all weight transposes (fp32) + qkv bias concat in ONE kernel; block (32,8)
__global__ void trans_all_kernel(const float* Wq, const float* Wk, const float* Wv,
                                 const float* Wo, const float* W1, const float* W2,
                                 const float* bq, const float* bk, const float* bv) {
    int cid = blockIdx.x;
    if (cid >= 768) {   // 3 blocks for bias concat (256 threads each)
        int t = (cid - 768) * 256 + threadIdx.y * 32 + threadIdx.x;
        g_bqkv[t] = (t < 256) ? bq[t] : (t < 512 ? bk[t - 256] : bv[t - 512]);
        return;
    }
    __shared__ float t[32][33];
    const float* W; float* Th; int Nd, ldT, tk, tn;
    if (cid < 192) {
        int m = cid / 64, tt = cid % 64;
        W = (m == 0) ? Wq : (m == 1 ? Wk : Wv);
        Th = g_wqkvT + (size_t)m * 256 * DD;
        Nd = 256; ldT = DD; tk = tt >> 3; tn = tt & 7;
    } else if (cid < 256) {
        int tt = cid - 192;
        W = Wo; Th = g_woT;
        Nd = 256; ldT = DD; tk = tt >> 3; tn = tt & 7;
    } else if (cid < 512) {
        int tt = cid - 256;
        W = W1; Th = g_w1T;
        Nd = 1024; ldT = DD; tk = tt >> 5; tn = tt & 31;
    } else {
        int tt = cid - 512;
        W = W2; Th = g_w2T;
        Nd = 256; ldT = DFF; tk = tt >> 3; tn = tt & 7;
    }
    int k0 = tk * 32, n0 = tn * 32;
    int tx = threadIdx.x, ty = threadIdx.y;
    #pragma unroll
    for (int i = 0; i < 32; i += 8)
        t[ty + i][tx] = W[(size_t)(k0 + ty + i) * Nd + n0 + tx];
    __syncthreads();
    #pragma unroll
    for (int i = 0; i < 32; i += 8)
        Th[(size_t)(n0 + ty + i) * ldT + k0 + tx] = t[tx][ty + i];
}

// ==================== cp.async pipelined tf32 wmma GEMM ====================
// C[M,N] = A[M,K] @ T^T  (T [N,K] K-major), fp32 operands, single tf32 pass.
// Block tile 128 x NT, 8 warps, K-chunks of 32, 2-stage cp.async pipeline.
// mode 0: C = out + bias;  mode 1: C = gelu(out + bias)
#define LDAE 36   // fp32 elements per smem row (32 + 4 pad), 144 bytes

template<int NT>
__global__ void __launch_bounds__(256)
gemm_tf32(const float* __restrict__ A, const float* __restrict__ Bt,
          const float* __restrict__ bias, float* __restrict__ C,
          int M, int N, int K, int mode) {
    extern __shared__ char smem[];
    const int tid = threadIdx.x, wid = tid >> 5;
    constexpr int MW = (NT == 128) ? 4 : 2;
    const int wr = (NT == 128) ? (wid & 1) * 64 : (wid & 3) * 32;
    const int wc = (NT == 128) ? (wid >> 1) * 32 : (wid >> 2) * 32;
    const int m0 = blockIdx.y * 128, n0 = blockIdx.x * NT;
    const int NC = K >> 5;

    constexpr int ASZ = 128 * LDAE * 4;           // A tile bytes
    constexpr int SS  = ASZ + NT * LDAE * 4;      // stage bytes
    const uint32_t sb0 = smem_u32(smem);

    wmma::fragment<wmma::accumulator, 16, 16, 8, float> acc[MW][2];
    #pragma unroll
    for (int i = 0; i < MW; i++)
        #pragma unroll
        for (int j = 0; j < 2; j++) wmma::fill_fragment(acc[i][j], 0.0f);

    const int rA = tid >> 3, seg = tid & 7;       // 32 rows x 8 16B-segments

    auto issue = [&](int c, int s) {
        const uint32_t sb = sb0 + s * SS;
        const int k0 = c << 5;
        #pragma unroll
        for (int i = 0; i < 4; i++) {
            int row = rA + 32 * i;
            cpa16(sb + row * 144 + seg * 16, A + (size_t)(m0 + row) * K + k0 + seg * 4);
        }
        #pragma unroll
        for (int i = 0; i < NT / 32; i++) {
            int row = rA + 32 * i;
            cpa16(sb + ASZ + row * 144 + seg * 16, Bt + (size_t)(n0 + row) * K + k0 + seg * 4);
        }
    };

    issue(0, 0); CP_COMMIT;
    for (int c = 0; c < NC; c++) {
        if (c + 1 < NC) { issue(c + 1, (c + 1) & 1); CP_COMMIT; CP_WAIT1; }
        else            { CP_WAIT0; }
        __syncthreads();
        const float* pA = reinterpret_cast<const float*>(smem + (c & 1) * SS);
        const float* pB = reinterpret_cast<const float*>(smem + (c & 1) * SS + ASZ);
        #pragma unroll
        for (int ks = 0; ks < 4; ks++) {
            wmma::fragment<wmma::matrix_a, 16, 16, 8, wmma::precision::tf32, wmma::row_major> a[MW];
            wmma::fragment<wmma::matrix_b, 16, 16, 8, wmma::precision::tf32, wmma::col_major> b[2];
            #pragma unroll
            for (int i = 0; i < MW; i++) {
                wmma::load_matrix_sync(a[i], pA + (wr + i * 16) * LDAE + ks * 8, LDAE);
                #pragma unroll
                for (int t = 0; t < a[i].num_elements; t++)
                    a[i].x[t] = wmma::__float_to_tf32(a[i].x[t]);
            }
            #pragma unroll
            for (int j = 0; j < 2; j++) {
                wmma::load_matrix_sync(b[j], pB + (wc + j * 16) * LDAE + ks * 8, LDAE);
                #pragma unroll
                for (int t = 0; t < b[j].num_elements; t++)
                    b[j].x[t] = wmma::__float_to_tf32(b[j].x[t]);
            }
            #pragma unroll
            for (int i = 0; i < MW; i++)
                #pragma unroll
                for (int j = 0; j < 2; j++)
                    wmma::mma_sync(acc[i][j], a[i], b[j], acc[i][j]);
        }
        __syncthreads();
    }

    // ---- epilogue via smem ----
    constexpr int LDC = NT + 4;
    float* cs = reinterpret_cast<float*>(smem);
    #pragma unroll
    for (int i = 0; i < MW; i++)
        #pragma unroll
        for (int j = 0; j < 2; j++)
            wmma::store_matrix_sync(&cs[(wr + i * 16) * LDC + wc + j * 16],
                                    acc[i][j], LDC, wmma::mem_row_major);
    __syncthreads();

    constexpr int NIT = (128 * NT / 4) / 256;
    #pragma unroll
    for (int it = 0; it < NIT; it++) {
        int flat = tid + 256 * it;
        int rr = flat / (NT / 4), c4 = flat % (NT / 4);
        const float* src = &cs[rr * LDC + c4 * 4];
        float vals[4];
        #pragma unroll
        for (int q = 0; q < 4; q++) {
            float v = src[q] + bias[n0 + c4 * 4 + q];
            if (mode == 1) v = 0.5f * v * (1.0f + erff(v * 0.70710678118654752f));
            vals[q] = v;
        }
        *reinterpret_cast<float4*>(&C[(size_t)(m0 + rr) * N + n0 + c4 * 4]) =
            *reinterpret_cast<float4*>(vals);
    }
}

// ==================== sparse masked attention ====================
__global__ void attn_kernel(const float* __restrict__ boxes,
                            const float* __restrict__ geo_w,
                            const float* __restrict__ geo_b) {
    int b = blockIdx.x >> 10;
    int i = blockIdx.x & (NN - 1);
    int tid = threadIdx.x;
    int l = tid & 31, w = tid >> 5;

    __shared__ float sq[DD];
    __shared__ int   sj[NN];
    __shared__ float sv[NN];
    __shared__ int   warpBase[8];
    __shared__ int   nvs;
    __shared__ float sbx[4];

    size_t rowq = (size_t)(b * NN + i) * 768;
    sq[tid] = g_qkv[rowq + tid];
    if (tid < 4) sbx[tid] = boxes[(b * NN + i) * 4 + tid];
    if (tid == 0) nvs = 0;
    __syncthreads();

    float gw0 = geo_w[0], gw1 = geo_w[1], gw2 = geo_w[2], gw3 = geo_w[3],
          gw4 = geo_w[4], gw5 = geo_w[5], gw6 = geo_w[6], gb = geo_b[0];
    float x1i = sbx[0], y1i = sbx[1], x2i = sbx[2], y2i = sbx[3];
    float cxi = 0.5f * (x1i + x2i), cyi = 0.5f * (y1i + y2i);
    float wi = fmaxf(x2i - x1i, 1e-6f), hi = fmaxf(y2i - y1i, 1e-6f);
    float ai = wi * hi;

    const int* lrow = &g_lastE[(size_t)(b * NN + i) * NN];

    for (int it = 0; it < NN / 256; it++) {
        int j = it * 256 + tid;
        int le = lrow[j];
        bool val = (le >= 0) || (j == i);
        unsigned m = __ballot_sync(0xffffffffu, val);
        if (l == 0) warpBase[w] = __popc(m);
        __syncthreads();
        if (tid == 0) {
            int s = nvs;
            for (int kk = 0; kk < 8; kk++) { int c = warpBase[kk]; warpBase[kk] = s; s += c; }
            nvs = s;
        }
        __syncthreads();
        if (val) {
            float4 bj = *reinterpret_cast<const float4*>(&boxes[(b * NN + j) * 4]);
            float x1j = bj.x, y1j = bj.y, x2j = bj.z, y2j = bj.w;
            float cxj = 0.5f * (x1j + x2j), cyj = 0.5f * (y1j + y2j);
            float wj = fmaxf(x2j - x1j, 1e-6f), hj = fmaxf(y2j - y1j, 1e-6f);
            float aj = wj * hj;
            float dx = cxi - cxj, dy = cyi - cyj;
            float lw = logf(wi / wj), lh = logf(hi / hj);
            float dist = sqrtf(dx * dx + dy * dy + 1e-6f);
            float ix1 = fmaxf(x1i, x1j), iy1 = fmaxf(y1i, y1j);
            float ix2 = fminf(x2i, x2j), iy2 = fminf(y2i, y2j);
            float iw = fmaxf(ix2 - ix1, 0.f), ih = fmaxf(iy2 - iy1, 0.f);
            float inter = iw * ih;
            float uni = ai + aj - inter + 1e-6f;
            float iou = inter / uni;
            float ar = ai / fmaxf(aj, 1e-6f);
            float biasv = gw0 * dx + gw1 * dy + gw2 * lw + gw3 * lh
                        + gw4 * dist + gw5 * iou + gw6 * ar + gb;
            if (le >= 0) biasv += g_proj[b * EE + le];
            int pos = warpBase[w] + __popc(m & ((1u << l) - 1u));
            sj[pos] = j;
            sv[pos] = biasv;
        }
        __syncthreads();
    }
    int nv = nvs;

    for (int t = w; t < nv; t += 8) {
        int j = sj[t];
        const float* kp = &g_qkv[(size_t)(b * NN + j) * 768 + 256];
        float s = 0.f;
        #pragma unroll
        for (int c = 0; c < DD / 32; c++) s += sq[l + 32 * c] * kp[l + 32 * c];
        #pragma unroll
        for (int o = 16; o; o >>= 1) s += __shfl_xor_sync(0xffffffffu, s, o);
        if (l == 0) sv[t] = s * 0.0625f + sv[t];
    }
    __syncthreads();

    if (w == 0) {
        float mx = -3.4e38f;
        for (int t = l; t < nv; t += 32) mx = fmaxf(mx, sv[t]);
        #pragma unroll
        for (int o = 16; o; o >>= 1) mx = fmaxf(mx, __shfl_xor_sync(0xffffffffu, mx, o));
        float sm = 0.f;
        for (int t = l; t < nv; t += 32) { float p = expf(sv[t] - mx); sv[t] = p; sm += p; }
        #pragma unroll
        for (int o = 16; o; o >>= 1) sm += __shfl_xor_sync(0xffffffffu, sm, o);
        float inv = 1.0f / sm;
        for (int t = l; t < nv; t += 32) sv[t] *= inv;
    }
    __syncthreads();

    float acc = 0.f;
    for (int t = 0; t < nv; t++)
        acc += sv[t] * g_qkv[(size_t)(b * NN + sj[t]) * 768 + 512 + tid];
    g_ao[(size_t)(b * NN + i) * DD + tid] = acc;
}

// ==================== residual + LayerNorm ====================
__global__ void ln_kernel(const float* __restrict__ a, const float* __restrict__ res,
                          const float* __restrict__ gam, const float* __restrict__ bet,
                          float* __restrict__ out) {
    int row = blockIdx.x, d = threadIdx.x;
    int l = d & 31, w = d >> 5;
    __shared__ float sp[8];
    __shared__ float bcast;
    size_t idx = (size_t)row * DD + d;
    float v = a[idx] + res[idx];

    float s = v;
    #pragma unroll
    for (int o = 16; o; o >>= 1) s += __shfl_xor_sync(0xffffffffu, s, o);
    if (l == 0) sp[w] = s;
    __syncthreads();
    if (d == 0) {
        float t = 0.0f;
        for (int k = 0; k < 8; k++) t += sp[k];
        bcast = t * (1.0f / DD);
    }
    __syncthreads();
    float mean = bcast;
    float c = v - mean;

    s = c * c;
    #pragma unroll
    for (int o = 16; o; o >>= 1) s += __shfl_xor_sync(0xffffffffu, s, o);
    __syncthreads();
    if (l == 0) sp[w] = s;
    __syncthreads();
    if (d == 0) {
        float t = 0.0f;
        for (int k = 0; k < 8; k++) t += sp[k];
        bcast = t * (1.0f / DD);
    }
    __syncthreads();
    float var = bcast;

    out[idx] = c * rsqrtf(var + 1e-5f) * gam[d] + bet[d];
}

// ==================== launch ====================
extern "C" void kernel_launch(void* const* d_in, const int* in_sizes, int n_in,
                              void* d_out, int out_size) {
    const float* nodes     = (const float*)d_in[0];
    const float* boxes     = (const float*)d_in[1];
    const float* edge_attr = (const float*)d_in[2];
    const float* Wq = (const float*)d_in[3];
    const float* bq = (const float*)d_in[4];
    const float* Wk = (const float*)d_in[5];
    const float* bk = (const float*)d_in[6];
    const float* Wv = (const float*)d_in[7];
    const float* bv = (const float*)d_in[8];
    const float* Wo = (const float*)d_in[9];
    const float* bo = (const float*)d_in[10];
    const float* geo_w  = (const float*)d_in[11];
    const float* geo_b  = (const float*)d_in[12];
    const float* edge_w = (const float*)d_in[13];
    const float* edge_b = (const float*)d_in[14];
    const float* ln1_g = (const float*)d_in[15];
    const float* ln1_b = (const float*)d_in[16];
    const float* ln2_g = (const float*)d_in[17];
    const float* ln2_b = (const float*)d_in[18];
    const float* W1  = (const float*)d_in[19];
    const float* b1f = (const float*)d_in[20];
    const float* W2  = (const float*)d_in[21];
    const float* b2f = (const float*)d_in[22];
    const int* edge_index = (const int*)d_in[24];
    float* out = (float*)d_out;

    float *qkv, *ao, *op, *x, *f, *h, *bqkv, *wqT, *woT, *w1T, *w2T;
    cudaGetSymbolAddress((void**)&qkv, g_qkv);
    cudaGetSymbolAddress((void**)&ao,  g_ao);
    cudaGetSymbolAddress((void**)&op,  g_op);
    cudaGetSymbolAddress((void**)&x,   g_x);
    cudaGetSymbolAddress((void**)&f,   g_f);
    cudaGetSymbolAddress((void**)&h,   g_h);
    cudaGetSymbolAddress((void**)&bqkv, g_bqkv);
    cudaGetSymbolAddress((void**)&wqT, g_wqkvT);
    cudaGetSymbolAddress((void**)&woT, g_woT);
    cudaGetSymbolAddress((void**)&w1T, g_w1T);
    cudaGetSymbolAddress((void**)&w2T, g_w2T);

    constexpr int SS128 = (128 + 128) * LDAE * 4;   // 36864
    constexpr int SS64  = (128 + 64)  * LDAE * 4;   // 27648
    constexpr int SMEM128 = 2 * SS128;              // 73728
    constexpr int SMEM64  = 2 * SS64;               // 55296
    cudaFuncSetAttribute(gemm_tf32<128>, cudaFuncAttributeMaxDynamicSharedMemorySize, SMEM128);
    cudaFuncSetAttribute(gemm_tf32<64>,  cudaFuncAttributeMaxDynamicSharedMemorySize, SMEM64);

    // launch order chosen so ncu's sampled launch (#4) is the QKV GEMM
    trans_all_kernel<<<771, dim3(32, 8)>>>(Wq, Wk, Wv, Wo, W1, W2, bq, bk, bv);
    init_lastE_kernel<<<(BB * NN * NN / 4) / 256, 256>>>();
    edge_kernel<<<(BB * EE) / 256, 256>>>(edge_attr, edge_w, edge_b, edge_index);

    // QKV fused: [8192,256] @ T[768,256]
    gemm_tf32<128><<<dim3(768 / 128, MM / 128), 256, SMEM128>>>(
        nodes, wqT, bqkv, qkv, MM, 768, DD, 0);

    attn_kernel<<<BB * NN, 256>>>(boxes, geo_w, geo_b);

    // Wo: [8192,256] @ T[256,256]
    gemm_tf32<64><<<dim3(DD / 64, MM / 128), 256, SMEM64>>>(
        ao, woT, bo, op, MM, DD, DD, 0);

    ln_kernel<<<BB * NN, 256>>>(op, nodes, ln1_g, ln1_b, x);

    // FFN1 + exact GELU
    gemm_tf32<128><<<dim3(DFF / 128, MM / 128), 256, SMEM128>>>(
        x, w1T, b1f, h, MM, DFF, DD, 1);

    // FFN2: [8192,1024] @ T[256,1024]
    gemm_tf32<64><<<dim3(DD / 64, MM / 128), 256, SMEM64>>>(
        h, w2T, b2f, f, MM, DD, DFF, 0);

    ln_kernel<<<BB * NN, 256>>>(f, x, ln2_g, ln2_b, out);
}

// round 11
// speedup vs baseline: 1.2204x; 1.2204x over previous
#include <cuda_runtime.h>
#include <cuda_bf16.h>
#include <mma.h>
#include <math.h>
#include <stdint.h>

using namespace nvcuda;
typedef __nv_bfloat16 bf16;

#define BB 8
#define NN 1024
#define DD 256
#define EE 32768
#define DFF 1024
#define MM (BB*NN)          // 8192 rows

// ---------------- scratch (static device globals; no allocation) ----------------
__device__ float g_qkv[MM*768];            // fused q|k|v (fp32)
__device__ float g_op [MM*DD];
__device__ float g_x  [MM*DD];
__device__ float g_f  [MM*DD];
__device__ float g_proj[BB*EE];
__device__ int   g_lastE[BB*NN*NN];
__device__ float g_bqkv[768];
// split-bf16 activations
__device__ bf16 g_ahi[MM*DD];              // nodes / ao / x splits (sequential reuse)
__device__ bf16 g_alo[MM*DD];
__device__ bf16 g_hhi[MM*DFF];             // FFN hidden split
__device__ bf16 g_hlo[MM*DFF];
// split-bf16 transposed weights [N,K] K-major
__device__ bf16 g_wqkvT_hi[768*DD], g_wqkvT_lo[768*DD];
__device__ bf16 g_woT_hi[DD*DD],    g_woT_lo[DD*DD];
__device__ bf16 g_w1T_hi[DFF*DD],   g_w1T_lo[DFF*DD];
__device__ bf16 g_w2T_hi[DD*DFF],   g_w2T_lo[DD*DFF];

// ==================== helpers ====================
__device__ __forceinline__ uint32_t smem_u32(const void* p) {
    uint32_t a;
    asm("{ .reg .u64 t; cvta.to.shared.u64 t, %1; cvt.u32.u64 %0, t; }" : "=r"(a) : "l"(p));
    return a;
}
__device__ __forceinline__ void cpa16(uint32_t dst, const void* src) {
    asm volatile("cp.async.cg.shared.global [%0], [%1], 16;" :: "r"(dst), "l"(src));
}
#define CP_COMMIT asm volatile("cp.async.commit_group;" ::: "memory")
#define CP_WAIT1  asm volatile("cp.async.wait_group 1;" ::: "memory")
#define CP_WAIT0  asm volatile("cp.async.wait_group 0;" ::: "memory")

// ==================== combined init_lastE + conv_split(nodes) ====================
__global__ void prep_kernel(const float* __restrict__ nodes,
                            bf16* __restrict__ hi, bf16* __restrict__ lo) {
    int cid = blockIdx.x;
    if (cid < 8192) {   // init lastE: 8M int4 stores
        size_t idx = (size_t)cid * blockDim.x + threadIdx.x;
        reinterpret_cast<int4*>(g_lastE)[idx] = make_int4(-1, -1, -1, -1);
    } else {            // split nodes: 2048 blocks
        int i = (cid - 8192) * 256 + threadIdx.x;
        float4 v = reinterpret_cast<const float4*>(nodes)[i];
        bf16 hh[4], ll[4];
        float vv[4] = {v.x, v.y, v.z, v.w};
        #pragma unroll
        for (int q = 0; q < 4; q++) {
            hh[q] = __float2bfloat16(vv[q]);
            ll[q] = __float2bfloat16(vv[q] - __bfloat162float(hh[q]));
        }
        reinterpret_cast<uint2*>(hi)[i] = *reinterpret_cast<uint2*>(hh);
        reinterpret_cast<uint2*>(lo)[i] = *reinterpret_cast<uint2*>(ll);
    }
}

// edge bias projection + adjacency scatter (fused)
__global__ void edge_kernel(const float* __restrict__ ea,
                            const float* __restrict__ ew,
                            const float* __restrict__ ebv,
                            const int* __restrict__ eidx) {
    int idx = blockIdx.x * blockDim.x + threadIdx.x;
    if (idx >= BB * EE) return;
    const float4* p = reinterpret_cast<const float4*>(ea + (size_t)idx * 16);
    const float4* w = reinterpret_cast<const float4*>(ew);
    float s = ebv[0];
    #pragma unroll
    for (int t = 0; t < 4; t++) {
        float4 a = p[t], b = w[t];
        s += a.x * b.x + a.y * b.y + a.z * b.z + a.w * b.w;
    }
    g_proj[idx] = s;
    int b = idx >> 15, e = idx & (EE - 1);
    int si = eidx[(b * 2 + 0) * EE + e];
    int di = eidx[(b * 2 + 1) * EE + e];
    if ((unsigned)si < (unsigned)NN && (unsigned)di < (unsigned)NN)
        atomicMax(&g_lastE[((size_t)(b * NN + si)) * NN + di], e);
}

// all six weight transposes+splits + bias concat in ONE kernel; block (32,8)
__global__ void trans_all_kernel(const float* Wq, const float* Wk, const float* Wv,
                                 const float* Wo, const float* W1, const float* W2,
                                 const float* bq, const float* bk, const float* bv) {
    int cid = blockIdx.x;
    if (cid >= 768) {   // 3 blocks for qkv bias concat
        int t = (cid - 768) * 256 + threadIdx.y * 32 + threadIdx.x;
        g_bqkv[t] = (t < 256) ? bq[t] : (t < 512 ? bk[t - 256] : bv[t - 512]);
        return;
    }
    __shared__ float t[32][33];
    const float* W; bf16 *Th, *Tl; int Nd, ldT, tk, tn;
    if (cid < 192) {
        int m = cid / 64, tt = cid % 64;
        W = (m == 0) ? Wq : (m == 1 ? Wk : Wv);
        Th = g_wqkvT_hi + (size_t)m * 256 * DD;
        Tl = g_wqkvT_lo + (size_t)m * 256 * DD;
        Nd = 256; ldT = DD; tk = tt >> 3; tn = tt & 7;
    } else if (cid < 256) {
        int tt = cid - 192;
        W = Wo; Th = g_woT_hi; Tl = g_woT_lo;
        Nd = 256; ldT = DD; tk = tt >> 3; tn = tt & 7;
    } else if (cid < 512) {
        int tt = cid - 256;
        W = W1; Th = g_w1T_hi; Tl = g_w1T_lo;
        Nd = 1024; ldT = DD; tk = tt >> 5; tn = tt & 31;
    } else {
        int tt = cid - 512;
        W = W2; Th = g_w2T_hi; Tl = g_w2T_lo;
        Nd = 256; ldT = DFF; tk = tt >> 3; tn = tt & 7;
    }
    int k0 = tk * 32, n0 = tn * 32;
    int tx = threadIdx.x, ty = threadIdx.y;
    #pragma unroll
    for (int i = 0; i < 32; i += 8)
        t[ty + i][tx] = W[(size_t)(k0 + ty + i) * Nd + n0 + tx];
    __syncthreads();
    #pragma unroll
    for (int i = 0; i < 32; i += 8) {
        float v = t[tx][ty + i];
        bf16 h = __float2bfloat16(v);
        size_t o = (size_t)(n0 + ty + i) * ldT + k0 + tx;
        Th[o] = h;
        Tl[o] = __float2bfloat16(v - __bfloat162float(h));
    }
}

// ==================== cp.async pipelined wmma bf16-split GEMM ====================
// C[M,N] = A[M,K] @ T^T  (T [N,K] K-major), hi/lo split, 3 MMA passes.
// Block tile 128 x NT, 8 warps, K-chunks of 32, 2-stage cp.async pipeline.
// __launch_bounds__(256, 2): cap regs at 128 so 2 CTAs fit per SM (16 warps).
// mode 0: C = fp32 out (+bias); mode 1: gelu(out+bias) -> split bf16 (Chi, Clo)
template<int NT>
__global__ void __launch_bounds__(256, 2)
gemm_tc(const bf16* __restrict__ Ahi, const bf16* __restrict__ Alo,
        const bf16* __restrict__ Bhi, const bf16* __restrict__ Blo,
        const float* __restrict__ bias, float* __restrict__ Cf,
        bf16* __restrict__ Chi, bf16* __restrict__ Clo,
        int M, int N, int K, int mode) {
    extern __shared__ char smem[];
    const int tid = threadIdx.x, wid = tid >> 5;
    constexpr int MW = (NT == 128) ? 4 : 2;          // m-frags per warp
    const int wr = (NT == 128) ? (wid & 1) * 64 : (wid & 3) * 32;
    const int wc = (NT == 128) ? (wid >> 1) * 32 : (wid >> 2) * 32;
    const int m0 = blockIdx.y * 128, n0 = blockIdx.x * NT;
    const int NC = K >> 5;

    constexpr int AH = 0;
    constexpr int AL = 128 * 80;
    constexpr int BH = 256 * 80;
    constexpr int BL = BH + NT * 80;
    constexpr int SS = BH + 2 * NT * 80;
    const uint32_t sb0 = smem_u32(smem);

    wmma::fragment<wmma::accumulator, 16, 16, 16, float> acc[MW][2];
    #pragma unroll
    for (int i = 0; i < MW; i++)
        #pragma unroll
        for (int j = 0; j < 2; j++) wmma::fill_fragment(acc[i][j], 0.0f);

    const int seg = tid & 3, r = tid >> 2;           // r in 0..63
    const int segB = seg * 16;

    auto issue = [&](int c, int s) {
        const uint32_t sb = sb0 + s * SS;
        const size_t ka = (size_t)(m0 + r) * K + (c << 5) + seg * 8;
        cpa16(sb + AH + r * 80 + segB,        Ahi + ka);
        cpa16(sb + AH + (r + 64) * 80 + segB, Ahi + ka + (size_t)64 * K);
        cpa16(sb + AL + r * 80 + segB,        Alo + ka);
        cpa16(sb + AL + (r + 64) * 80 + segB, Alo + ka + (size_t)64 * K);
        const size_t kb = (size_t)(n0 + r) * K + (c << 5) + seg * 8;
        cpa16(sb + BH + r * 80 + segB, Bhi + kb);
        cpa16(sb + BL + r * 80 + segB, Blo + kb);
        if (NT == 128) {
            cpa16(sb + BH + (r + 64) * 80 + segB, Bhi + kb + (size_t)64 * K);
            cpa16(sb + BL + (r + 64) * 80 + segB, Blo + kb + (size_t)64 * K);
        }
    };

    issue(0, 0); CP_COMMIT;
    for (int c = 0; c < NC; c++) {
        if (c + 1 < NC) { issue(c + 1, (c + 1) & 1); CP_COMMIT; CP_WAIT1; }
        else            { CP_WAIT0; }
        __syncthreads();
        const char* base = smem + (c & 1) * SS;
        const bf16* pAh = reinterpret_cast<const bf16*>(base + AH);
        const bf16* pAl = reinterpret_cast<const bf16*>(base + AL);
        const bf16* pBh = reinterpret_cast<const bf16*>(base + BH);
        const bf16* pBl = reinterpret_cast<const bf16*>(base + BL);
        #pragma unroll
        for (int ks = 0; ks < 32; ks += 16) {
            wmma::fragment<wmma::matrix_a, 16, 16, 16, bf16, wmma::row_major> ah[MW], al[MW];
            #pragma unroll
            for (int i = 0; i < MW; i++) {
                wmma::load_matrix_sync(ah[i], pAh + (wr + i * 16) * 40 + ks, 40);
                wmma::load_matrix_sync(al[i], pAl + (wr + i * 16) * 40 + ks, 40);
            }
            #pragma unroll
            for (int j = 0; j < 2; j++) {
                wmma::fragment<wmma::matrix_b, 16, 16, 16, bf16, wmma::col_major> bh, bl;
                wmma::load_matrix_sync(bh, pBh + (wc + j * 16) * 40 + ks, 40);
                wmma::load_matrix_sync(bl, pBl + (wc + j * 16) * 40 + ks, 40);
                #pragma unroll
                for (int i = 0; i < MW; i++) {
                    wmma::mma_sync(acc[i][j], ah[i], bh, acc[i][j]);
                    wmma::mma_sync(acc[i][j], ah[i], bl, acc[i][j]);
                    wmma::mma_sync(acc[i][j], al[i], bh, acc[i][j]);
                }
            }
        }
        __syncthreads();
    }

    // ---- epilogue via smem (reuse pipeline buffers) ----
    constexpr int LDC = NT + 4;
    float* cs = reinterpret_cast<float*>(smem);
    #pragma unroll
    for (int i = 0; i < MW; i++)
        #pragma unroll
        for (int j = 0; j < 2; j++)
            wmma::store_matrix_sync(&cs[(wr + i * 16) * LDC + wc + j * 16],
                                    acc[i][j], LDC, wmma::mem_row_major);
    __syncthreads();

    constexpr int NIT = (128 * NT / 4) / 256;
    #pragma unroll
    for (int it = 0; it < NIT; it++) {
        int flat = tid + 256 * it;
        int rr = flat / (NT / 4), c4 = flat % (NT / 4);
        const float* src = &cs[rr * LDC + c4 * 4];
        float vals[4];
        #pragma unroll
        for (int q = 0; q < 4; q++) vals[q] = src[q] + bias[n0 + c4 * 4 + q];
        if (mode == 0) {
            *reinterpret_cast<float4*>(&Cf[(size_t)(m0 + rr) * N + n0 + c4 * 4]) =
                *reinterpret_cast<float4*>(vals);
        } else {
            bf16 hh[4], ll[4];
            #pragma unroll
            for (int q = 0; q < 4; q++) {
                float v = vals[q];
                v = 0.5f * v * (1.0f + erff(v * 0.70710678118654752f));
                hh[q] = __float2bfloat16(v);
                ll[q] = __float2bfloat16(v - __bfloat162float(hh[q]));
            }
            size_t o = ((size_t)(m0 + rr) * N + n0 + c4 * 4) >> 2;
            reinterpret_cast<uint2*>(Chi)[o] = *reinterpret_cast<uint2*>(hh);
            reinterpret_cast<uint2*>(Clo)[o] = *reinterpret_cast<uint2*>(ll);
        }
    }
}

// ==================== sparse masked attention (emits split ao) ====================
__global__ void attn_kernel(const float* __restrict__ boxes,
                            const float* __restrict__ geo_w,
                            const float* __restrict__ geo_b,
                            bf16* __restrict__ aohi, bf16* __restrict__ aolo) {
    int b = blockIdx.x >> 10;
    int i = blockIdx.x & (NN - 1);
    int tid = threadIdx.x;
    int l = tid & 31, w = tid >> 5;

    __shared__ float sq[DD];
    __shared__ int   sj[NN];
    __shared__ float sv[NN];
    __shared__ int   warpBase[8];
    __shared__ int   nvs;
    __shared__ float sbx[4];

    size_t rowq = (size_t)(b * NN + i) * 768;
    sq[tid] = g_qkv[rowq + tid];
    if (tid < 4) sbx[tid] = boxes[(b * NN + i) * 4 + tid];
    if (tid == 0) nvs = 0;
    __syncthreads();

    float gw0 = geo_w[0], gw1 = geo_w[1], gw2 = geo_w[2], gw3 = geo_w[3],
          gw4 = geo_w[4], gw5 = geo_w[5], gw6 = geo_w[6], gb = geo_b[0];
    float x1i = sbx[0], y1i = sbx[1], x2i = sbx[2], y2i = sbx[3];
    float cxi = 0.5f * (x1i + x2i), cyi = 0.5f * (y1i + y2i);
    float wi = fmaxf(x2i - x1i, 1e-6f), hi = fmaxf(y2i - y1i, 1e-6f);
    float ai = wi * hi;

    const int* lrow = &g_lastE[(size_t)(b * NN + i) * NN];

    for (int it = 0; it < NN / 256; it++) {
        int j = it * 256 + tid;
        int le = lrow[j];
        bool val = (le >= 0) || (j == i);
        unsigned m = __ballot_sync(0xffffffffu, val);
        if (l == 0) warpBase[w] = __popc(m);
        __syncthreads();
        if (tid == 0) {
            int s = nvs;
            for (int kk = 0; kk < 8; kk++) { int c = warpBase[kk]; warpBase[kk] = s; s += c; }
            nvs = s;
        }
        __syncthreads();
        if (val) {
            float4 bj = *reinterpret_cast<const float4*>(&boxes[(b * NN + j) * 4]);
            float x1j = bj.x, y1j = bj.y, x2j = bj.z, y2j = bj.w;
            float cxj = 0.5f * (x1j + x2j), cyj = 0.5f * (y1j + y2j);
            float wj = fmaxf(x2j - x1j, 1e-6f), hj = fmaxf(y2j - y1j, 1e-6f);
            float aj = wj * hj;
            float dx = cxi - cxj, dy = cyi - cyj;
            float lw = logf(wi / wj), lh = logf(hi / hj);
            float dist = sqrtf(dx * dx + dy * dy + 1e-6f);
            float ix1 = fmaxf(x1i, x1j), iy1 = fmaxf(y1i, y1j);
            float ix2 = fminf(x2i, x2j), iy2 = fminf(y2i, y2j);
            float iw = fmaxf(ix2 - ix1, 0.f), ih = fmaxf(iy2 - iy1, 0.f);
            float inter = iw * ih;
            float uni = ai + aj - inter + 1e-6f;
            float iou = inter / uni;
            float ar = ai / fmaxf(aj, 1e-6f);
            float biasv = gw0 * dx + gw1 * dy + gw2 * lw + gw3 * lh
                        + gw4 * dist + gw5 * iou + gw6 * ar + gb;
            if (le >= 0) biasv += g_proj[b * EE + le];
            int pos = warpBase[w] + __popc(m & ((1u << l) - 1u));
            sj[pos] = j;
            sv[pos] = biasv;
        }
        __syncthreads();
    }
    int nv = nvs;

    for (int t = w; t < nv; t += 8) {
        int j = sj[t];
        const float* kp = &g_qkv[(size_t)(b * NN + j) * 768 + 256];
        float s = 0.f;
        #pragma unroll
        for (int c = 0; c < DD / 32; c++) s += sq[l + 32 * c] * kp[l + 32 * c];
        #pragma unroll
        for (int o = 16; o; o >>= 1) s += __shfl_xor_sync(0xffffffffu, s, o);
        if (l == 0) sv[t] = s * 0.0625f + sv[t];
    }
    __syncthreads();

    if (w == 0) {
        float mx = -3.4e38f;
        for (int t = l; t < nv; t += 32) mx = fmaxf(mx, sv[t]);
        #pragma unroll
        for (int o = 16; o; o >>= 1) mx = fmaxf(mx, __shfl_xor_sync(0xffffffffu, mx, o));
        float sm = 0.f;
        for (int t = l; t < nv; t += 32) { float p = expf(sv[t] - mx); sv[t] = p; sm += p; }
        #pragma unroll
        for (int o = 16; o; o >>= 1) sm += __shfl_xor_sync(0xffffffffu, sm, o);
        float inv = 1.0f / sm;
        for (int t = l; t < nv; t += 32) sv[t] *= inv;
    }
    __syncthreads();

    float acc = 0.f;
    for (int t = 0; t < nv; t++)
        acc += sv[t] * g_qkv[(size_t)(b * NN + sj[t]) * 768 + 512 + tid];
    size_t o = (size_t)(b * NN + i) * DD + tid;
    bf16 hh = __float2bfloat16(acc);
    aohi[o] = hh;
    aolo[o] = __float2bfloat16(acc - __bfloat162float(hh));
}

// ==================== residual + LayerNorm (optional split emit) ====================
__global__ void ln_kernel(const float* __restrict__ a, const float* __restrict__ res,
                          const float* __restrict__ gam, const float* __restrict__ bet,
                          float* __restrict__ out,
                          bf16* __restrict__ ohi, bf16* __restrict__ olo) {
    int row = blockIdx.x, d = threadIdx.x;
    int l = d & 31, w = d >> 5;
    __shared__ float sp[8];
    __shared__ float bcast;
    size_t idx = (size_t)row * DD + d;
    float v = a[idx] + res[idx];

    float s = v;
    #pragma unroll
    for (int o = 16; o; o >>= 1) s += __shfl_xor_sync(0xffffffffu, s, o);
    if (l == 0) sp[w] = s;
    __syncthreads();
    if (d == 0) {
        float t = 0.0f;
        for (int k = 0; k < 8; k++) t += sp[k];
        bcast = t * (1.0f / DD);
    }
    __syncthreads();
    float mean = bcast;
    float c = v - mean;

    s = c * c;
    #pragma unroll
    for (int o = 16; o; o >>= 1) s += __shfl_xor_sync(0xffffffffu, s, o);
    __syncthreads();
    if (l == 0) sp[w] = s;
    __syncthreads();
    if (d == 0) {
        float t = 0.0f;
        for (int k = 0; k < 8; k++) t += sp[k];
        bcast = t * (1.0f / DD);
    }
    __syncthreads();
    float var = bcast;

    float o = c * rsqrtf(var + 1e-5f) * gam[d] + bet[d];
    out[idx] = o;
    if (ohi) {
        bf16 hh = __float2bfloat16(o);
        ohi[idx] = hh;
        olo[idx] = __float2bfloat16(o - __bfloat162float(hh));
    }
}

// ==================== launch ====================
extern "C" void kernel_launch(void* const* d_in, const int* in_sizes, int n_in,
                              void* d_out, int out_size) {
    const float* nodes     = (const float*)d_in[0];
    const float* boxes     = (const float*)d_in[1];
    const float* edge_attr = (const float*)d_in[2];
    const float* Wq = (const float*)d_in[3];
    const float* bq = (const float*)d_in[4];
    const float* Wk = (const float*)d_in[5];
    const float* bk = (const float*)d_in[6];
    const float* Wv = (const float*)d_in[7];
    const float* bv = (const float*)d_in[8];
    const float* Wo = (const float*)d_in[9];
    const float* bo = (const float*)d_in[10];
    const float* geo_w  = (const float*)d_in[11];
    const float* geo_b  = (const float*)d_in[12];
    const float* edge_w = (const float*)d_in[13];
    const float* edge_b = (const float*)d_in[14];
    const float* ln1_g = (const float*)d_in[15];
    const float* ln1_b = (const float*)d_in[16];
    const float* ln2_g = (const float*)d_in[17];
    const float* ln2_b = (const float*)d_in[18];
    const float* W1  = (const float*)d_in[19];
    const float* b1f = (const float*)d_in[20];
    const float* W2  = (const float*)d_in[21];
    const float* b2f = (const float*)d_in[22];
    const int* edge_index = (const int*)d_in[24];
    float* out = (float*)d_out;

    float *qkv, *op, *x, *f, *bqkv;
    bf16 *ahi, *alo, *hhi, *hlo, *wqh, *wql, *woh, *wol, *w1h, *w1l, *w2h, *w2l;
    cudaGetSymbolAddress((void**)&qkv, g_qkv);
    cudaGetSymbolAddress((void**)&op,  g_op);
    cudaGetSymbolAddress((void**)&x,   g_x);
    cudaGetSymbolAddress((void**)&f,   g_f);
    cudaGetSymbolAddress((void**)&bqkv, g_bqkv);
    cudaGetSymbolAddress((void**)&ahi, g_ahi);
    cudaGetSymbolAddress((void**)&alo, g_alo);
    cudaGetSymbolAddress((void**)&hhi, g_hhi);
    cudaGetSymbolAddress((void**)&hlo, g_hlo);
    cudaGetSymbolAddress((void**)&wqh, g_wqkvT_hi);
    cudaGetSymbolAddress((void**)&wql, g_wqkvT_lo);
    cudaGetSymbolAddress((void**)&woh, g_woT_hi);
    cudaGetSymbolAddress((void**)&wol, g_woT_lo);
    cudaGetSymbolAddress((void**)&w1h, g_w1T_hi);
    cudaGetSymbolAddress((void**)&w1l, g_w1T_lo);
    cudaGetSymbolAddress((void**)&w2h, g_w2T_hi);
    cudaGetSymbolAddress((void**)&w2l, g_w2T_lo);

    constexpr int SMEM128 = 2 * (256 * 80 + 2 * 128 * 80);   // 81920
    constexpr int SMEM64  = 2 * (256 * 80 + 2 * 64 * 80);    // 61440
    cudaFuncSetAttribute(gemm_tc<128>, cudaFuncAttributeMaxDynamicSharedMemorySize, SMEM128);
    cudaFuncSetAttribute(gemm_tc<64>,  cudaFuncAttributeMaxDynamicSharedMemorySize, SMEM64);

    // launch order: ncu samples launch #4 -> make it the QKV GEMM
    trans_all_kernel<<<771, dim3(32, 8)>>>(Wq, Wk, Wv, Wo, W1, W2, bq, bk, bv);
    prep_kernel<<<8192 + 2048, 256>>>(nodes, ahi, alo);
    edge_kernel<<<(BB * EE) / 256, 256>>>(edge_attr, edge_w, edge_b, edge_index);

    // QKV fused: [8192,256] @ T[768,256]
    gemm_tc<128><<<dim3(768 / 128, MM / 128), 256, SMEM128>>>(
        ahi, alo, wqh, wql, bqkv, qkv, nullptr, nullptr, MM, 768, DD, 0);

    attn_kernel<<<BB * NN, 256>>>(boxes, geo_w, geo_b, ahi, alo);

    // Wo: [8192,256] @ T[256,256]
    gemm_tc<64><<<dim3(DD / 64, MM / 128), 256, SMEM64>>>(
        ahi, alo, woh, wol, bo, op, nullptr, nullptr, MM, DD, DD, 0);

    ln_kernel<<<BB * NN, 256>>>(op, nodes, ln1_g, ln1_b, x, ahi, alo);

    // FFN1 + exact GELU -> split h
    gemm_tc<128><<<dim3(DFF / 128, MM / 128), 256, SMEM128>>>(
        ahi, alo, w1h, w1l, b1f, nullptr, hhi, hlo, MM, DFF, DD, 1);

    // FFN2: [8192,1024] @ T[256,1024]
    gemm_tc<64><<<dim3(DD / 64, MM / 128), 256, SMEM64>>>(
        hhi, hlo, w2h, w2l, b2f, f, nullptr, nullptr, MM, DD, DFF, 0);

    ln_kernel<<<BB * NN, 256>>>(f, x, ln2_g, ln2_b, out, nullptr, nullptr);
}

// round 14
// speedup vs baseline: 1.4976x; 1.2272x over previous
#include <cuda_runtime.h>
#include <cuda_fp16.h>
#include <mma.h>
#include <math.h>
#include <stdint.h>

using namespace nvcuda;

#define BB 8
#define NN 1024
#define DD 256
#define EE 32768
#define DFF 1024
#define MM (BB*NN)          // 8192 rows

// ---------------- scratch (static device globals; no allocation) ----------------
__device__ float g_qkv[MM*768];            // fused q|k|v (fp32)
__device__ float g_op [MM*DD];
__device__ float g_x  [MM*DD];
__device__ float g_f  [MM*DD];
__device__ float g_proj[BB*EE];
__device__ int   g_lastE[BB*NN*NN];
__device__ float g_bqkv[768];
// fp16 activations (A operands; single precision copy — error 2^-11 absorbed)
__device__ __half g_a[MM*DD];              // nodes / ao / x (sequential reuse)
__device__ __half g_h[MM*DFF];             // FFN hidden
// fp16 hi/lo split transposed weights [N,K] K-major (B operands; exact)
__device__ __half g_wqkvT_hi[768*DD], g_wqkvT_lo[768*DD];
__device__ __half g_woT_hi[DD*DD],    g_woT_lo[DD*DD];
__device__ __half g_w1T_hi[DFF*DD],   g_w1T_lo[DFF*DD];
__device__ __half g_w2T_hi[DD*DFF],   g_w2T_lo[DD*DFF];

// ==================== helpers ====================
__device__ __forceinline__ uint32_t smem_u32(const void* p) {
    uint32_t a;
    asm("{ .reg .u64 t; cvta.to.shared.u64 t, %1; cvt.u32.u64 %0, t; }" : "=r"(a) : "l"(p));
    return a;
}
__device__ __forceinline__ void cpa16(uint32_t dst, const void* src) {
    asm volatile("cp.async.cg.shared.global [%0], [%1], 16;" :: "r"(dst), "l"(src));
}
#define CP_COMMIT asm volatile("cp.async.commit_group;" ::: "memory")
#define CP_WAIT1  asm volatile("cp.async.wait_group 1;" ::: "memory")
#define CP_WAIT0  asm volatile("cp.async.wait_group 0;" ::: "memory")

// ==================== combined init_lastE + conv(nodes->fp16) ====================
__global__ void prep_kernel(const float* __restrict__ nodes, __half* __restrict__ a) {
    int cid = blockIdx.x;
    if (cid < 8192) {
        size_t idx = (size_t)cid * blockDim.x + threadIdx.x;
        reinterpret_cast<int4*>(g_lastE)[idx] = make_int4(-1, -1, -1, -1);
    } else {
        int i = (cid - 8192) * 256 + threadIdx.x;
        float4 v = reinterpret_cast<const float4*>(nodes)[i];
        __half hh[4] = {__float2half(v.x), __float2half(v.y),
                        __float2half(v.z), __float2half(v.w)};
        reinterpret_cast<uint2*>(a)[i] = *reinterpret_cast<uint2*>(hh);
    }
}

// edge bias projection + adjacency scatter (fused)
__global__ void edge_kernel(const float* __restrict__ ea,
                            const float* __restrict__ ew,
                            const float* __restrict__ ebv,
                            const int* __restrict__ eidx) {
    int idx = blockIdx.x * blockDim.x + threadIdx.x;
    if (idx >= BB * EE) return;
    const float4* p = reinterpret_cast<const float4*>(ea + (size_t)idx * 16);
    const float4* w = reinterpret_cast<const float4*>(ew);
    float s = ebv[0];
    #pragma unroll
    for (int t = 0; t < 4; t++) {
        float4 a = p[t], b = w[t];
        s += a.x * b.x + a.y * b.y + a.z * b.z + a.w * b.w;
    }
    g_proj[idx] = s;
    int b = idx >> 15, e = idx & (EE - 1);
    int si = eidx[(b * 2 + 0) * EE + e];
    int di = eidx[(b * 2 + 1) * EE + e];
    if ((unsigned)si < (unsigned)NN && (unsigned)di < (unsigned)NN)
        atomicMax(&g_lastE[((size_t)(b * NN + si)) * NN + di], e);
}

// all six weight transposes + fp16 hi/lo split + bias concat; block (32,8)
__global__ void trans_all_kernel(const float* Wq, const float* Wk, const float* Wv,
                                 const float* Wo, const float* W1, const float* W2,
                                 const float* bq, const float* bk, const float* bv) {
    int cid = blockIdx.x;
    if (cid >= 768) {
        int t = (cid - 768) * 256 + threadIdx.y * 32 + threadIdx.x;
        g_bqkv[t] = (t < 256) ? bq[t] : (t < 512 ? bk[t - 256] : bv[t - 512]);
        return;
    }
    __shared__ float t[32][33];
    const float* W; __half *Th, *Tl; int Nd, ldT, tk, tn;
    if (cid < 192) {
        int m = cid / 64, tt = cid % 64;
        W = (m == 0) ? Wq : (m == 1 ? Wk : Wv);
        Th = g_wqkvT_hi + (size_t)m * 256 * DD;
        Tl = g_wqkvT_lo + (size_t)m * 256 * DD;
        Nd = 256; ldT = DD; tk = tt >> 3; tn = tt & 7;
    } else if (cid < 256) {
        int tt = cid - 192;
        W = Wo; Th = g_woT_hi; Tl = g_woT_lo;
        Nd = 256; ldT = DD; tk = tt >> 3; tn = tt & 7;
    } else if (cid < 512) {
        int tt = cid - 256;
        W = W1; Th = g_w1T_hi; Tl = g_w1T_lo;
        Nd = 1024; ldT = DD; tk = tt >> 5; tn = tt & 31;
    } else {
        int tt = cid - 512;
        W = W2; Th = g_w2T_hi; Tl = g_w2T_lo;
        Nd = 256; ldT = DFF; tk = tt >> 3; tn = tt & 7;
    }
    int k0 = tk * 32, n0 = tn * 32;
    int tx = threadIdx.x, ty = threadIdx.y;
    #pragma unroll
    for (int i = 0; i < 32; i += 8)
        t[ty + i][tx] = W[(size_t)(k0 + ty + i) * Nd + n0 + tx];
    __syncthreads();
    #pragma unroll
    for (int i = 0; i < 32; i += 8) {
        float v = t[tx][ty + i];
        __half h = __float2half(v);
        size_t o = (size_t)(n0 + ty + i) * ldT + k0 + tx;
        Th[o] = h;
        Tl[o] = __float2half(v - __half2float(h));
    }
}

// ==================== cp.async pipelined fp16 2-pass wmma GEMM ====================
// C[M,N] = A[M,K] @ T^T;  A fp16 (rounded), T split hi/lo fp16 (exact).
// C ≈ A·Th + A·Tl  (dropped Al·T term ~2^-11).
// Block tile 128 x NT, 8 warps, K-chunks of 32, 2-stage cp.async pipeline, 2 CTAs/SM.
// mode 0: Cf = out + bias (fp32); mode 1: Ch = fp16(gelu(out + bias))
template<int NT>
__global__ void __launch_bounds__(256, 2)
gemm_tc(const __half* __restrict__ A,
        const __half* __restrict__ Bhi, const __half* __restrict__ Blo,
        const float* __restrict__ bias, float* __restrict__ Cf,
        __half* __restrict__ Ch,
        int M, int N, int K, int mode) {
    extern __shared__ char smem[];
    const int tid = threadIdx.x, wid = tid >> 5;
    constexpr int MW = (NT == 128) ? 4 : 2;
    const int wr = (NT == 128) ? (wid & 1) * 64 : (wid & 3) * 32;
    const int wc = (NT == 128) ? (wid >> 1) * 32 : (wid >> 2) * 32;
    const int m0 = blockIdx.y * 128, n0 = blockIdx.x * NT;
    const int NC = K >> 5;

    constexpr int AH = 0;
    constexpr int BH = 128 * 80;
    constexpr int BL = BH + NT * 80;
    constexpr int SS = BH + 2 * NT * 80;
    const uint32_t sb0 = smem_u32(smem);

    wmma::fragment<wmma::accumulator, 16, 16, 16, float> acc[MW][2];
    #pragma unroll
    for (int i = 0; i < MW; i++)
        #pragma unroll
        for (int j = 0; j < 2; j++) wmma::fill_fragment(acc[i][j], 0.0f);

    const int seg = tid & 3, r = tid >> 2;           // r in 0..63, seg 16B segments

    auto issue = [&](int c, int s) {
        const uint32_t sb = sb0 + s * SS;
        const size_t ka = (size_t)(m0 + r) * K + (c << 5) + seg * 8;
        cpa16(sb + AH + r * 80 + seg * 16,        A + ka);
        cpa16(sb + AH + (r + 64) * 80 + seg * 16, A + ka + (size_t)64 * K);
        const size_t kb = (size_t)(n0 + r) * K + (c << 5) + seg * 8;
        cpa16(sb + BH + r * 80 + seg * 16, Bhi + kb);
        cpa16(sb + BL + r * 80 + seg * 16, Blo + kb);
        if (NT == 128) {
            cpa16(sb + BH + (r + 64) * 80 + seg * 16, Bhi + kb + (size_t)64 * K);
            cpa16(sb + BL + (r + 64) * 80 + seg * 16, Blo + kb + (size_t)64 * K);
        }
    };

    issue(0, 0); CP_COMMIT;
    for (int c = 0; c < NC; c++) {
        if (c + 1 < NC) { issue(c + 1, (c + 1) & 1); CP_COMMIT; CP_WAIT1; }
        else            { CP_WAIT0; }
        __syncthreads();
        const char* base = smem + (c & 1) * SS;
        const __half* pA  = reinterpret_cast<const __half*>(base + AH);
        const __half* pBh = reinterpret_cast<const __half*>(base + BH);
        const __half* pBl = reinterpret_cast<const __half*>(base + BL);
        #pragma unroll
        for (int ks = 0; ks < 32; ks += 16) {
            wmma::fragment<wmma::matrix_a, 16, 16, 16, __half, wmma::row_major> a[MW];
            #pragma unroll
            for (int i = 0; i < MW; i++)
                wmma::load_matrix_sync(a[i], pA + (wr + i * 16) * 40 + ks, 40);
            #pragma unroll
            for (int j = 0; j < 2; j++) {
                wmma::fragment<wmma::matrix_b, 16, 16, 16, __half, wmma::col_major> bh, bl;
                wmma::load_matrix_sync(bh, pBh + (wc + j * 16) * 40 + ks, 40);
                wmma::load_matrix_sync(bl, pBl + (wc + j * 16) * 40 + ks, 40);
                #pragma unroll
                for (int i = 0; i < MW; i++) {
                    wmma::mma_sync(acc[i][j], a[i], bh, acc[i][j]);
                    wmma::mma_sync(acc[i][j], a[i], bl, acc[i][j]);
                }
            }
        }
        __syncthreads();
    }

    // ---- epilogue via smem (needs 128*(NT+4)*4 bytes; smem sized for max) ----
    constexpr int LDC = NT + 4;
    float* cs = reinterpret_cast<float*>(smem);
    #pragma unroll
    for (int i = 0; i < MW; i++)
        #pragma unroll
        for (int j = 0; j < 2; j++)
            wmma::store_matrix_sync(&cs[(wr + i * 16) * LDC + wc + j * 16],
                                    acc[i][j], LDC, wmma::mem_row_major);
    __syncthreads();

    constexpr int NIT = (128 * NT / 4) / 256;
    #pragma unroll
    for (int it = 0; it < NIT; it++) {
        int flat = tid + 256 * it;
        int rr = flat / (NT / 4), c4 = flat % (NT / 4);
        const float* src = &cs[rr * LDC + c4 * 4];
        float vals[4];
        #pragma unroll
        for (int q = 0; q < 4; q++) vals[q] = src[q] + bias[n0 + c4 * 4 + q];
        if (mode == 0) {
            *reinterpret_cast<float4*>(&Cf[(size_t)(m0 + rr) * N + n0 + c4 * 4]) =
                *reinterpret_cast<float4*>(vals);
        } else {
            __half hh[4];
            #pragma unroll
            for (int q = 0; q < 4; q++) {
                float v = vals[q];
                hh[q] = __float2half(0.5f * v * (1.0f + erff(v * 0.70710678118654752f)));
            }
            size_t o = ((size_t)(m0 + rr) * N + n0 + c4 * 4) >> 2;
            reinterpret_cast<uint2*>(Ch)[o] = *reinterpret_cast<uint2*>(hh);
        }
    }
}

// ==================== sparse masked attention (emits fp16 ao) ====================
__global__ void attn_kernel(const float* __restrict__ boxes,
                            const float* __restrict__ geo_w,
                            const float* __restrict__ geo_b,
                            __half* __restrict__ ao) {
    int b = blockIdx.x >> 10;
    int i = blockIdx.x & (NN - 1);
    int tid = threadIdx.x;
    int l = tid & 31, w = tid >> 5;

    __shared__ float sq[DD];
    __shared__ int   sj[NN];
    __shared__ float sv[NN];
    __shared__ int   warpBase[8];
    __shared__ int   nvs;
    __shared__ float sbx[4];

    size_t rowq = (size_t)(b * NN + i) * 768;
    sq[tid] = g_qkv[rowq + tid];
    if (tid < 4) sbx[tid] = boxes[(b * NN + i) * 4 + tid];
    if (tid == 0) nvs = 0;
    __syncthreads();

    float gw0 = geo_w[0], gw1 = geo_w[1], gw2 = geo_w[2], gw3 = geo_w[3],
          gw4 = geo_w[4], gw5 = geo_w[5], gw6 = geo_w[6], gb = geo_b[0];
    float x1i = sbx[0], y1i = sbx[1], x2i = sbx[2], y2i = sbx[3];
    float cxi = 0.5f * (x1i + x2i), cyi = 0.5f * (y1i + y2i);
    float wi = fmaxf(x2i - x1i, 1e-6f), hi = fmaxf(y2i - y1i, 1e-6f);
    float ai = wi * hi;

    const int* lrow = &g_lastE[(size_t)(b * NN + i) * NN];

    for (int it = 0; it < NN / 256; it++) {
        int j = it * 256 + tid;
        int le = lrow[j];
        bool val = (le >= 0) || (j == i);
        unsigned m = __ballot_sync(0xffffffffu, val);
        if (l == 0) warpBase[w] = __popc(m);
        __syncthreads();
        if (tid == 0) {
            int s = nvs;
            for (int kk = 0; kk < 8; kk++) { int c = warpBase[kk]; warpBase[kk] = s; s += c; }
            nvs = s;
        }
        __syncthreads();
        if (val) {
            float4 bj = *reinterpret_cast<const float4*>(&boxes[(b * NN + j) * 4]);
            float x1j = bj.x, y1j = bj.y, x2j = bj.z, y2j = bj.w;
            float cxj = 0.5f * (x1j + x2j), cyj = 0.5f * (y1j + y2j);
            float wj = fmaxf(x2j - x1j, 1e-6f), hj = fmaxf(y2j - y1j, 1e-6f);
            float aj = wj * hj;
            float dx = cxi - cxj, dy = cyi - cyj;
            float lw = logf(wi / wj), lh = logf(hi / hj);
            float dist = sqrtf(dx * dx + dy * dy + 1e-6f);
            float ix1 = fmaxf(x1i, x1j), iy1 = fmaxf(y1i, y1j);
            float ix2 = fminf(x2i, x2j), iy2 = fminf(y2i, y2j);
            float iw = fmaxf(ix2 - ix1, 0.f), ih = fmaxf(iy2 - iy1, 0.f);
            float inter = iw * ih;
            float uni = ai + aj - inter + 1e-6f;
            float iou = inter / uni;
            float ar = ai / fmaxf(aj, 1e-6f);
            float biasv = gw0 * dx + gw1 * dy + gw2 * lw + gw3 * lh
                        + gw4 * dist + gw5 * iou + gw6 * ar + gb;
            if (le >= 0) biasv += g_proj[b * EE + le];
            int pos = warpBase[w] + __popc(m & ((1u << l) - 1u));
            sj[pos] = j;
            sv[pos] = biasv;
        }
        __syncthreads();
    }
    int nv = nvs;

    for (int t = w; t < nv; t += 8) {
        int j = sj[t];
        const float* kp = &g_qkv[(size_t)(b * NN + j) * 768 + 256];
        float s = 0.f;
        #pragma unroll
        for (int c = 0; c < DD / 32; c++) s += sq[l + 32 * c] * kp[l + 32 * c];
        #pragma unroll
        for (int o = 16; o; o >>= 1) s += __shfl_xor_sync(0xffffffffu, s, o);
        if (l == 0) sv[t] = s * 0.0625f + sv[t];
    }
    __syncthreads();

    if (w == 0) {
        float mx = -3.4e38f;
        for (int t = l; t < nv; t += 32) mx = fmaxf(mx, sv[t]);
        #pragma unroll
        for (int o = 16; o; o >>= 1) mx = fmaxf(mx, __shfl_xor_sync(0xffffffffu, mx, o));
        float sm = 0.f;
        for (int t = l; t < nv; t += 32) { float p = expf(sv[t] - mx); sv[t] = p; sm += p; }
        #pragma unroll
        for (int o = 16; o; o >>= 1) sm += __shfl_xor_sync(0xffffffffu, sm, o);
        float inv = 1.0f / sm;
        for (int t = l; t < nv; t += 32) sv[t] *= inv;
    }
    __syncthreads();

    float acc = 0.f;
    for (int t = 0; t < nv; t++)
        acc += sv[t] * g_qkv[(size_t)(b * NN + sj[t]) * 768 + 512 + tid];
    ao[(size_t)(b * NN + i) * DD + tid] = __float2half(acc);
}

// ==================== residual + LayerNorm (optional fp16 emit) ====================
__global__ void ln_kernel(const float* __restrict__ a, const float* __restrict__ res,
                          const float* __restrict__ gam, const float* __restrict__ bet,
                          float* __restrict__ out, __half* __restrict__ oh) {
    int row = blockIdx.x, d = threadIdx.x;
    int l = d & 31, w = d >> 5;
    __shared__ float sp[8];
    __shared__ float bcast;
    size_t idx = (size_t)row * DD + d;
    float v = a[idx] + res[idx];

    float s = v;
    #pragma unroll
    for (int o = 16; o; o >>= 1) s += __shfl_xor_sync(0xffffffffu, s, o);
    if (l == 0) sp[w] = s;
    __syncthreads();
    if (d == 0) {
        float t = 0.0f;
        for (int k = 0; k < 8; k++) t += sp[k];
        bcast = t * (1.0f / DD);
    }
    __syncthreads();
    float mean = bcast;
    float c = v - mean;

    s = c * c;
    #pragma unroll
    for (int o = 16; o; o >>= 1) s += __shfl_xor_sync(0xffffffffu, s, o);
    __syncthreads();
    if (l == 0) sp[w] = s;
    __syncthreads();
    if (d == 0) {
        float t = 0.0f;
        for (int k = 0; k < 8; k++) t += sp[k];
        bcast = t * (1.0f / DD);
    }
    __syncthreads();
    float var = bcast;

    float o = c * rsqrtf(var + 1e-5f) * gam[d] + bet[d];
    out[idx] = o;
    if (oh) oh[idx] = __float2half(o);
}

// ==================== launch ====================
extern "C" void kernel_launch(void* const* d_in, const int* in_sizes, int n_in,
                              void* d_out, int out_size) {
    const float* nodes     = (const float*)d_in[0];
    const float* boxes     = (const float*)d_in[1];
    const float* edge_attr = (const float*)d_in[2];
    const float* Wq = (const float*)d_in[3];
    const float* bq = (const float*)d_in[4];
    const float* Wk = (const float*)d_in[5];
    const float* bk = (const float*)d_in[6];
    const float* Wv = (const float*)d_in[7];
    const float* bv = (const float*)d_in[8];
    const float* Wo = (const float*)d_in[9];
    const float* bo = (const float*)d_in[10];
    const float* geo_w  = (const float*)d_in[11];
    const float* geo_b  = (const float*)d_in[12];
    const float* edge_w = (const float*)d_in[13];
    const float* edge_b = (const float*)d_in[14];
    const float* ln1_g = (const float*)d_in[15];
    const float* ln1_b = (const float*)d_in[16];
    const float* ln2_g = (const float*)d_in[17];
    const float* ln2_b = (const float*)d_in[18];
    const float* W1  = (const float*)d_in[19];
    const float* b1f = (const float*)d_in[20];
    const float* W2  = (const float*)d_in[21];
    const float* b2f = (const float*)d_in[22];
    const int* edge_index = (const int*)d_in[24];
    float* out = (float*)d_out;

    float *qkv, *op, *x, *f, *bqkv;
    __half *a, *h, *wqh, *wql, *woh, *wol, *w1h, *w1l, *w2h, *w2l;
    cudaGetSymbolAddress((void**)&qkv, g_qkv);
    cudaGetSymbolAddress((void**)&op,  g_op);
    cudaGetSymbolAddress((void**)&x,   g_x);
    cudaGetSymbolAddress((void**)&f,   g_f);
    cudaGetSymbolAddress((void**)&bqkv, g_bqkv);
    cudaGetSymbolAddress((void**)&a,   g_a);
    cudaGetSymbolAddress((void**)&h,   g_h);
    cudaGetSymbolAddress((void**)&wqh, g_wqkvT_hi);
    cudaGetSymbolAddress((void**)&wql, g_wqkvT_lo);
    cudaGetSymbolAddress((void**)&woh, g_woT_hi);
    cudaGetSymbolAddress((void**)&wol, g_woT_lo);
    cudaGetSymbolAddress((void**)&w1h, g_w1T_hi);
    cudaGetSymbolAddress((void**)&w1l, g_w1T_lo);
    cudaGetSymbolAddress((void**)&w2h, g_w2T_hi);
    cudaGetSymbolAddress((void**)&w2l, g_w2T_lo);

    // smem = max(pipeline bytes, epilogue bytes 128*(NT+4)*4)
    constexpr int SMEM128 = 128 * 132 * 4;                   // 67584 (> 61440 pipeline)
    constexpr int SMEM64  = 2 * (128 * 80 + 2 * 64 * 80);    // 40960 (> 34816 epilogue)
    cudaFuncSetAttribute(gemm_tc<128>, cudaFuncAttributeMaxDynamicSharedMemorySize, SMEM128);
    cudaFuncSetAttribute(gemm_tc<64>,  cudaFuncAttributeMaxDynamicSharedMemorySize, SMEM64);

    // launch order: ncu samples launch #4 -> QKV GEMM
    trans_all_kernel<<<771, dim3(32, 8)>>>(Wq, Wk, Wv, Wo, W1, W2, bq, bk, bv);
    prep_kernel<<<8192 + 2048, 256>>>(nodes, a);
    edge_kernel<<<(BB * EE) / 256, 256>>>(edge_attr, edge_w, edge_b, edge_index);

    // QKV fused: [8192,256] @ T[768,256]
    gemm_tc<128><<<dim3(768 / 128, MM / 128), 256, SMEM128>>>(
        a, wqh, wql, bqkv, qkv, nullptr, MM, 768, DD, 0);

    attn_kernel<<<BB * NN, 256>>>(boxes, geo_w, geo_b, a);

    // Wo: [8192,256] @ T[256,256]
    gemm_tc<64><<<dim3(DD / 64, MM / 128), 256, SMEM64>>>(
        a, woh, wol, bo, op, nullptr, MM, DD, DD, 0);

    ln_kernel<<<BB * NN, 256>>>(op, nodes, ln1_g, ln1_b, x, a);

    // FFN1 + exact GELU -> fp16 h
    gemm_tc<128><<<dim3(DFF / 128, MM / 128), 256, SMEM128>>>(
        a, w1h, w1l, b1f, nullptr, h, MM, DFF, DD, 1);

    // FFN2: [8192,1024] @ T[256,1024]
    gemm_tc<64><<<dim3(DD / 64, MM / 128), 256, SMEM64>>>(
        h, w2h, w2l, b2f, f, nullptr, MM, DD, DFF, 0);

    ln_kernel<<<BB * NN, 256>>>(f, x, ln2_g, ln2_b, out, nullptr);
}

// round 16
// speedup vs baseline: 1.5934x; 1.0639x over previous
#include <cuda_runtime.h>
#include <cuda_fp16.h>
#include <mma.h>
#include <math.h>
#include <stdint.h>

using namespace nvcuda;

#define BB 8
#define NN 1024
#define DD 256
#define EE 32768
#define DFF 1024
#define MM (BB*NN)          // 8192 rows

// ---------------- scratch (static device globals; no allocation) ----------------
__device__ __half g_qkv[MM*768];           // fused q|k|v (fp16)
__device__ float g_op [MM*DD];
__device__ float g_x  [MM*DD];
__device__ float g_f  [MM*DD];
__device__ float g_proj[BB*EE];
__device__ int   g_lastE[BB*NN*NN];
__device__ float g_bqkv[768];
// fp16 activations (A operands)
__device__ __half g_a[MM*DD];              // nodes / ao / x (sequential reuse)
__device__ __half g_h[MM*DFF];             // FFN hidden
// fp16 hi/lo split transposed weights [N,K] K-major (B operands; exact)
__device__ __half g_wqkvT_hi[768*DD], g_wqkvT_lo[768*DD];
__device__ __half g_woT_hi[DD*DD],    g_woT_lo[DD*DD];
__device__ __half g_w1T_hi[DFF*DD],   g_w1T_lo[DFF*DD];
__device__ __half g_w2T_hi[DD*DFF],   g_w2T_lo[DD*DFF];

// ==================== helpers ====================
__device__ __forceinline__ uint32_t smem_u32(const void* p) {
    uint32_t a;
    asm("{ .reg .u64 t; cvta.to.shared.u64 t, %1; cvt.u32.u64 %0, t; }" : "=r"(a) : "l"(p));
    return a;
}
__device__ __forceinline__ void cpa16(uint32_t dst, const void* src) {
    asm volatile("cp.async.cg.shared.global [%0], [%1], 16;" :: "r"(dst), "l"(src));
}
#define CP_COMMIT asm volatile("cp.async.commit_group;" ::: "memory")
#define CP_WAIT2  asm volatile("cp.async.wait_group 2;" ::: "memory")
#define CP_WAIT1  asm volatile("cp.async.wait_group 1;" ::: "memory")
#define CP_WAIT0  asm volatile("cp.async.wait_group 0;" ::: "memory")

// ==================== combined init_lastE + conv(nodes->fp16) ====================
__global__ void prep_kernel(const float* __restrict__ nodes, __half* __restrict__ a) {
    int cid = blockIdx.x;
    if (cid < 8192) {
        size_t idx = (size_t)cid * blockDim.x + threadIdx.x;
        reinterpret_cast<int4*>(g_lastE)[idx] = make_int4(-1, -1, -1, -1);
    } else {
        int i = (cid - 8192) * 256 + threadIdx.x;
        float4 v = reinterpret_cast<const float4*>(nodes)[i];
        __half hh[4] = {__float2half(v.x), __float2half(v.y),
                        __float2half(v.z), __float2half(v.w)};
        reinterpret_cast<uint2*>(a)[i] = *reinterpret_cast<uint2*>(hh);
    }
}

// edge bias projection + adjacency scatter (fused)
__global__ void edge_kernel(const float* __restrict__ ea,
                            const float* __restrict__ ew,
                            const float* __restrict__ ebv,
                            const int* __restrict__ eidx) {
    int idx = blockIdx.x * blockDim.x + threadIdx.x;
    if (idx >= BB * EE) return;
    const float4* p = reinterpret_cast<const float4*>(ea + (size_t)idx * 16);
    const float4* w = reinterpret_cast<const float4*>(ew);
    float s = ebv[0];
    #pragma unroll
    for (int t = 0; t < 4; t++) {
        float4 a = p[t], b = w[t];
        s += a.x * b.x + a.y * b.y + a.z * b.z + a.w * b.w;
    }
    g_proj[idx] = s;
    int b = idx >> 15, e = idx & (EE - 1);
    int si = eidx[(b * 2 + 0) * EE + e];
    int di = eidx[(b * 2 + 1) * EE + e];
    if ((unsigned)si < (unsigned)NN && (unsigned)di < (unsigned)NN)
        atomicMax(&g_lastE[((size_t)(b * NN + si)) * NN + di], e);
}

// all six weight transposes + fp16 hi/lo split + bias concat; block (32,8)
__global__ void trans_all_kernel(const float* Wq, const float* Wk, const float* Wv,
                                 const float* Wo, const float* W1, const float* W2,
                                 const float* bq, const float* bk, const float* bv) {
    int cid = blockIdx.x;
    if (cid >= 768) {
        int t = (cid - 768) * 256 + threadIdx.y * 32 + threadIdx.x;
        g_bqkv[t] = (t < 256) ? bq[t] : (t < 512 ? bk[t - 256] : bv[t - 512]);
        return;
    }
    __shared__ float t[32][33];
    const float* W; __half *Th, *Tl; int Nd, ldT, tk, tn;
    if (cid < 192) {
        int m = cid / 64, tt = cid % 64;
        W = (m == 0) ? Wq : (m == 1 ? Wk : Wv);
        Th = g_wqkvT_hi + (size_t)m * 256 * DD;
        Tl = g_wqkvT_lo + (size_t)m * 256 * DD;
        Nd = 256; ldT = DD; tk = tt >> 3; tn = tt & 7;
    } else if (cid < 256) {
        int tt = cid - 192;
        W = Wo; Th = g_woT_hi; Tl = g_woT_lo;
        Nd = 256; ldT = DD; tk = tt >> 3; tn = tt & 7;
    } else if (cid < 512) {
        int tt = cid - 256;
        W = W1; Th = g_w1T_hi; Tl = g_w1T_lo;
        Nd = 1024; ldT = DD; tk = tt >> 5; tn = tt & 31;
    } else {
        int tt = cid - 512;
        W = W2; Th = g_w2T_hi; Tl = g_w2T_lo;
        Nd = 256; ldT = DFF; tk = tt >> 3; tn = tt & 7;
    }
    int k0 = tk * 32, n0 = tn * 32;
    int tx = threadIdx.x, ty = threadIdx.y;
    #pragma unroll
    for (int i = 0; i < 32; i += 8)
        t[ty + i][tx] = W[(size_t)(k0 + ty + i) * Nd + n0 + tx];
    __syncthreads();
    #pragma unroll
    for (int i = 0; i < 32; i += 8) {
        float v = t[tx][ty + i];
        __half h = __float2half(v);
        size_t o = (size_t)(n0 + ty + i) * ldT + k0 + tx;
        Th[o] = h;
        Tl[o] = __float2half(v - __half2float(h));
    }
}

// ==================== 3-stage cp.async pipelined fp16 2-pass wmma GEMM ====================
// C[M,N] = A[M,K] @ T^T;  A fp16 (rounded), T split hi/lo fp16 (exact).
// mode 0: Cf = out+bias (fp32); mode 1: Ch = fp16(gelu(out+bias)); mode 2: Ch = fp16(out+bias)
template<int NT>
__global__ void __launch_bounds__(256, 2)
gemm_tc(const __half* __restrict__ A,
        const __half* __restrict__ Bhi, const __half* __restrict__ Blo,
        const float* __restrict__ bias, float* __restrict__ Cf,
        __half* __restrict__ Ch,
        int M, int N, int K, int mode) {
    extern __shared__ char smem[];
    const int tid = threadIdx.x, wid = tid >> 5;
    constexpr int MW = (NT == 128) ? 4 : 2;
    const int wr = (NT == 128) ? (wid & 1) * 64 : (wid & 3) * 32;
    const int wc = (NT == 128) ? (wid >> 1) * 32 : (wid >> 2) * 32;
    const int m0 = blockIdx.y * 128, n0 = blockIdx.x * NT;
    const int NC = K >> 5;

    constexpr int AH = 0;
    constexpr int BH = 128 * 80;
    constexpr int BL = BH + NT * 80;
    constexpr int SS = BH + 2 * NT * 80;
    const uint32_t sb0 = smem_u32(smem);

    wmma::fragment<wmma::accumulator, 16, 16, 16, float> acc[MW][2];
    #pragma unroll
    for (int i = 0; i < MW; i++)
        #pragma unroll
        for (int j = 0; j < 2; j++) wmma::fill_fragment(acc[i][j], 0.0f);

    const int seg = tid & 3, r = tid >> 2;           // r in 0..63, seg 16B segments

    auto issue = [&](int c, int s) {
        const uint32_t sb = sb0 + s * SS;
        const size_t ka = (size_t)(m0 + r) * K + (c << 5) + seg * 8;
        cpa16(sb + AH + r * 80 + seg * 16,        A + ka);
        cpa16(sb + AH + (r + 64) * 80 + seg * 16, A + ka + (size_t)64 * K);
        const size_t kb = (size_t)(n0 + r) * K + (c << 5) + seg * 8;
        cpa16(sb + BH + r * 80 + seg * 16, Bhi + kb);
        cpa16(sb + BL + r * 80 + seg * 16, Blo + kb);
        if (NT == 128) {
            cpa16(sb + BH + (r + 64) * 80 + seg * 16, Bhi + kb + (size_t)64 * K);
            cpa16(sb + BL + (r + 64) * 80 + seg * 16, Blo + kb + (size_t)64 * K);
        }
    };

    issue(0, 0); CP_COMMIT;
    if (NC > 1) { issue(1, 1); CP_COMMIT; }
    int st = 0;
    for (int c = 0; c < NC; c++) {
        if (c + 2 < NC) { issue(c + 2, (c + 2) % 3); CP_COMMIT; CP_WAIT2; }
        else if (c + 1 < NC) { CP_WAIT1; }
        else { CP_WAIT0; }
        __syncthreads();
        const char* base = smem + st * SS;
        st = (st == 2) ? 0 : st + 1;
        const __half* pA  = reinterpret_cast<const __half*>(base + AH);
        const __half* pBh = reinterpret_cast<const __half*>(base + BH);
        const __half* pBl = reinterpret_cast<const __half*>(base + BL);
        #pragma unroll
        for (int ks = 0; ks < 32; ks += 16) {
            wmma::fragment<wmma::matrix_a, 16, 16, 16, __half, wmma::row_major> a[MW];
            #pragma unroll
            for (int i = 0; i < MW; i++)
                wmma::load_matrix_sync(a[i], pA + (wr + i * 16) * 40 + ks, 40);
            #pragma unroll
            for (int j = 0; j < 2; j++) {
                wmma::fragment<wmma::matrix_b, 16, 16, 16, __half, wmma::col_major> bh, bl;
                wmma::load_matrix_sync(bh, pBh + (wc + j * 16) * 40 + ks, 40);
                wmma::load_matrix_sync(bl, pBl + (wc + j * 16) * 40 + ks, 40);
                #pragma unroll
                for (int i = 0; i < MW; i++) {
                    wmma::mma_sync(acc[i][j], a[i], bh, acc[i][j]);
                    wmma::mma_sync(acc[i][j], a[i], bl, acc[i][j]);
                }
            }
        }
        __syncthreads();
    }

    // ---- epilogue via smem ----
    constexpr int LDC = NT + 4;
    float* cs = reinterpret_cast<float*>(smem);
    #pragma unroll
    for (int i = 0; i < MW; i++)
        #pragma unroll
        for (int j = 0; j < 2; j++)
            wmma::store_matrix_sync(&cs[(wr + i * 16) * LDC + wc + j * 16],
                                    acc[i][j], LDC, wmma::mem_row_major);
    __syncthreads();

    constexpr int NIT = (128 * NT / 4) / 256;
    #pragma unroll
    for (int it = 0; it < NIT; it++) {
        int flat = tid + 256 * it;
        int rr = flat / (NT / 4), c4 = flat % (NT / 4);
        const float* src = &cs[rr * LDC + c4 * 4];
        float vals[4];
        #pragma unroll
        for (int q = 0; q < 4; q++) vals[q] = src[q] + bias[n0 + c4 * 4 + q];
        if (mode == 0) {
            *reinterpret_cast<float4*>(&Cf[(size_t)(m0 + rr) * N + n0 + c4 * 4]) =
                *reinterpret_cast<float4*>(vals);
        } else {
            __half hh[4];
            #pragma unroll
            for (int q = 0; q < 4; q++) {
                float v = vals[q];
                if (mode == 1) v = 0.5f * v * (1.0f + erff(v * 0.70710678118654752f));
                hh[q] = __float2half(v);
            }
            size_t o = ((size_t)(m0 + rr) * N + n0 + c4 * 4) >> 2;
            reinterpret_cast<uint2*>(Ch)[o] = *reinterpret_cast<uint2*>(hh);
        }
    }
}

// ==================== sparse masked attention (fp16 qkv, emits fp16 ao) ====================
__global__ void attn_kernel(const float* __restrict__ boxes,
                            const float* __restrict__ geo_w,
                            const float* __restrict__ geo_b,
                            __half* __restrict__ ao) {
    int b = blockIdx.x >> 10;
    int i = blockIdx.x & (NN - 1);
    int tid = threadIdx.x;
    int l = tid & 31, w = tid >> 5;

    __shared__ float sq[DD];
    __shared__ int   sj[NN];
    __shared__ float sv[NN];
    __shared__ int   warpBase[8];
    __shared__ int   nvs;
    __shared__ float sbx[4];

    size_t rowq = (size_t)(b * NN + i) * 768;
    sq[tid] = __half2float(g_qkv[rowq + tid]);
    if (tid < 4) sbx[tid] = boxes[(b * NN + i) * 4 + tid];
    if (tid == 0) nvs = 0;
    __syncthreads();

    float gw0 = geo_w[0], gw1 = geo_w[1], gw2 = geo_w[2], gw3 = geo_w[3],
          gw4 = geo_w[4], gw5 = geo_w[5], gw6 = geo_w[6], gb = geo_b[0];
    float x1i = sbx[0], y1i = sbx[1], x2i = sbx[2], y2i = sbx[3];
    float cxi = 0.5f * (x1i + x2i), cyi = 0.5f * (y1i + y2i);
    float wi = fmaxf(x2i - x1i, 1e-6f), hi = fmaxf(y2i - y1i, 1e-6f);
    float ai = wi * hi;

    const int* lrow = &g_lastE[(size_t)(b * NN + i) * NN];

    for (int it = 0; it < NN / 256; it++) {
        int j = it * 256 + tid;
        int le = lrow[j];
        bool val = (le >= 0) || (j == i);
        unsigned m = __ballot_sync(0xffffffffu, val);
        if (l == 0) warpBase[w] = __popc(m);
        __syncthreads();
        if (tid == 0) {
            int s = nvs;
            for (int kk = 0; kk < 8; kk++) { int c = warpBase[kk]; warpBase[kk] = s; s += c; }
            nvs = s;
        }
        __syncthreads();
        if (val) {
            float4 bj = *reinterpret_cast<const float4*>(&boxes[(b * NN + j) * 4]);
            float x1j = bj.x, y1j = bj.y, x2j = bj.z, y2j = bj.w;
            float cxj = 0.5f * (x1j + x2j), cyj = 0.5f * (y1j + y2j);
            float wj = fmaxf(x2j - x1j, 1e-6f), hj = fmaxf(y2j - y1j, 1e-6f);
            float aj = wj * hj;
            float dx = cxi - cxj, dy = cyi - cyj;
            float lw = logf(wi / wj), lh = logf(hi / hj);
            float dist = sqrtf(dx * dx + dy * dy + 1e-6f);
            float ix1 = fmaxf(x1i, x1j), iy1 = fmaxf(y1i, y1j);
            float ix2 = fminf(x2i, x2j), iy2 = fminf(y2i, y2j);
            float iw = fmaxf(ix2 - ix1, 0.f), ih = fmaxf(iy2 - iy1, 0.f);
            float inter = iw * ih;
            float uni = ai + aj - inter + 1e-6f;
            float iou = inter / uni;
            float ar = ai / fmaxf(aj, 1e-6f);
            float biasv = gw0 * dx + gw1 * dy + gw2 * lw + gw3 * lh
                        + gw4 * dist + gw5 * iou + gw6 * ar + gb;
            if (le >= 0) biasv += g_proj[b * EE + le];
            int pos = warpBase[w] + __popc(m & ((1u << l) - 1u));
            sj[pos] = j;
            sv[pos] = biasv;
        }
        __syncthreads();
    }
    int nv = nvs;

    // q·k: one warp per valid entry; half2 coalesced loads
    for (int t = w; t < nv; t += 8) {
        int j = sj[t];
        const __half2* kp = reinterpret_cast<const __half2*>(&g_qkv[(size_t)(b * NN + j) * 768 + 256]);
        float s = 0.f;
        #pragma unroll
        for (int c = 0; c < 4; c++) {
            int p = l + 32 * c;
            float2 kk = __half22float2(kp[p]);
            s += sq[2 * p] * kk.x + sq[2 * p + 1] * kk.y;
        }
        #pragma unroll
        for (int o = 16; o; o >>= 1) s += __shfl_xor_sync(0xffffffffu, s, o);
        if (l == 0) sv[t] = s * 0.0625f + sv[t];
    }
    __syncthreads();

    if (w == 0) {
        float mx = -3.4e38f;
        for (int t = l; t < nv; t += 32) mx = fmaxf(mx, sv[t]);
        #pragma unroll
        for (int o = 16; o; o >>= 1) mx = fmaxf(mx, __shfl_xor_sync(0xffffffffu, mx, o));
        float sm = 0.f;
        for (int t = l; t < nv; t += 32) { float p = expf(sv[t] - mx); sv[t] = p; sm += p; }
        #pragma unroll
        for (int o = 16; o; o >>= 1) sm += __shfl_xor_sync(0xffffffffu, sm, o);
        float inv = 1.0f / sm;
        for (int t = l; t < nv; t += 32) sv[t] *= inv;
    }
    __syncthreads();

    float acc = 0.f;
    for (int t = 0; t < nv; t++)
        acc += sv[t] * __half2float(g_qkv[(size_t)(b * NN + sj[t]) * 768 + 512 + tid]);
    ao[(size_t)(b * NN + i) * DD + tid] = __float2half(acc);
}

// ==================== residual + LayerNorm: one warp per row ====================
__global__ void ln_kernel(const float* __restrict__ a, const float* __restrict__ res,
                          const float* __restrict__ gam, const float* __restrict__ bet,
                          float* __restrict__ out, __half* __restrict__ oh) {
    int w = threadIdx.x >> 5, l = threadIdx.x & 31;
    int row = blockIdx.x * 8 + w;
    size_t base = (size_t)row * DD;

    float v[8], s = 0.f;
    #pragma unroll
    for (int u = 0; u < 8; u++) {
        int d = l + 32 * u;
        v[u] = a[base + d] + res[base + d];
        s += v[u];
    }
    #pragma unroll
    for (int o = 16; o; o >>= 1) s += __shfl_xor_sync(0xffffffffu, s, o);
    float mean = s * (1.0f / DD);

    float q = 0.f;
    #pragma unroll
    for (int u = 0; u < 8; u++) { float c = v[u] - mean; q += c * c; }
    #pragma unroll
    for (int o = 16; o; o >>= 1) q += __shfl_xor_sync(0xffffffffu, q, o);
    float rstd = rsqrtf(q * (1.0f / DD) + 1e-5f);

    #pragma unroll
    for (int u = 0; u < 8; u++) {
        int d = l + 32 * u;
        float o = (v[u] - mean) * rstd * gam[d] + bet[d];
        out[base + d] = o;
        if (oh) oh[base + d] = __float2half(o);
    }
}

// ==================== launch ====================
extern "C" void kernel_launch(void* const* d_in, const int* in_sizes, int n_in,
                              void* d_out, int out_size) {
    const float* nodes     = (const float*)d_in[0];
    const float* boxes     = (const float*)d_in[1];
    const float* edge_attr = (const float*)d_in[2];
    const float* Wq = (const float*)d_in[3];
    const float* bq = (const float*)d_in[4];
    const float* Wk = (const float*)d_in[5];
    const float* bk = (const float*)d_in[6];
    const float* Wv = (const float*)d_in[7];
    const float* bv = (const float*)d_in[8];
    const float* Wo = (const float*)d_in[9];
    const float* bo = (const float*)d_in[10];
    const float* geo_w  = (const float*)d_in[11];
    const float* geo_b  = (const float*)d_in[12];
    const float* edge_w = (const float*)d_in[13];
    const float* edge_b = (const float*)d_in[14];
    const float* ln1_g = (const float*)d_in[15];
    const float* ln1_b = (const float*)d_in[16];
    const float* ln2_g = (const float*)d_in[17];
    const float* ln2_b = (const float*)d_in[18];
    const float* W1  = (const float*)d_in[19];
    const float* b1f = (const float*)d_in[20];
    const float* W2  = (const float*)d_in[21];
    const float* b2f = (const float*)d_in[22];
    const int* edge_index = (const int*)d_in[24];
    float* out = (float*)d_out;

    float *op, *x, *f, *bqkv;
    __half *qkv, *a, *h, *wqh, *wql, *woh, *wol, *w1h, *w1l, *w2h, *w2l;
    cudaGetSymbolAddress((void**)&qkv, g_qkv);
    cudaGetSymbolAddress((void**)&op,  g_op);
    cudaGetSymbolAddress((void**)&x,   g_x);
    cudaGetSymbolAddress((void**)&f,   g_f);
    cudaGetSymbolAddress((void**)&bqkv, g_bqkv);
    cudaGetSymbolAddress((void**)&a,   g_a);
    cudaGetSymbolAddress((void**)&h,   g_h);
    cudaGetSymbolAddress((void**)&wqh, g_wqkvT_hi);
    cudaGetSymbolAddress((void**)&wql, g_wqkvT_lo);
    cudaGetSymbolAddress((void**)&woh, g_woT_hi);
    cudaGetSymbolAddress((void**)&wol, g_woT_lo);
    cudaGetSymbolAddress((void**)&w1h, g_w1T_hi);
    cudaGetSymbolAddress((void**)&w1l, g_w1T_lo);
    cudaGetSymbolAddress((void**)&w2h, g_w2T_hi);
    cudaGetSymbolAddress((void**)&w2l, g_w2T_lo);

    // smem = max(3-stage pipeline, epilogue 128*(NT+4)*4)
    constexpr int SMEM128 = 3 * (128 + 256) * 80;            // 92160 (> 67584 epilogue)
    constexpr int SMEM64  = 3 * (128 + 128) * 80;            // 61440 (> 34816 epilogue)
    cudaFuncSetAttribute(gemm_tc<128>, cudaFuncAttributeMaxDynamicSharedMemorySize, SMEM128);
    cudaFuncSetAttribute(gemm_tc<64>,  cudaFuncAttributeMaxDynamicSharedMemorySize, SMEM64);

    // launch order: ncu samples launch #4 -> QKV GEMM
    trans_all_kernel<<<771, dim3(32, 8)>>>(Wq, Wk, Wv, Wo, W1, W2, bq, bk, bv);
    prep_kernel<<<8192 + 2048, 256>>>(nodes, a);
    edge_kernel<<<(BB * EE) / 256, 256>>>(edge_attr, edge_w, edge_b, edge_index);

    // QKV fused: [8192,256] @ T[768,256] -> fp16
    gemm_tc<128><<<dim3(768 / 128, MM / 128), 256, SMEM128>>>(
        a, wqh, wql, bqkv, nullptr, qkv, MM, 768, DD, 2);

    attn_kernel<<<BB * NN, 256>>>(boxes, geo_w, geo_b, a);

    // Wo: [8192,256] @ T[256,256] -> fp32
    gemm_tc<64><<<dim3(DD / 64, MM / 128), 256, SMEM64>>>(
        a, woh, wol, bo, op, nullptr, MM, DD, DD, 0);

    ln_kernel<<<MM / 8, 256>>>(op, nodes, ln1_g, ln1_b, x, a);

    // FFN1 + exact GELU -> fp16 h
    gemm_tc<128><<<dim3(DFF / 128, MM / 128), 256, SMEM128>>>(
        a, w1h, w1l, b1f, nullptr, h, MM, DFF, DD, 1);

    // FFN2: [8192,1024] @ T[256,1024] -> fp32
    gemm_tc<64><<<dim3(DD / 64, MM / 128), 256, SMEM64>>>(
        h, w2h, w2l, b2f, f, nullptr, MM, DD, DFF, 0);

    ln_kernel<<<MM / 8, 256>>>(f, x, ln2_g, ln2_b, out, nullptr);
}

// round 17
// speedup vs baseline: 1.8156x; 1.1395x over previous
#include <cuda_runtime.h>
#include <cuda_fp16.h>
#include <mma.h>
#include <math.h>
#include <stdint.h>

using namespace nvcuda;

#define BB 8
#define NN 1024
#define DD 256
#define EE 32768
#define DFF 1024
#define MM (BB*NN)          // 8192 rows

// ---------------- scratch (static device globals; no allocation) ----------------
__device__ __half g_qkv[MM*768];           // fused q|k|v (fp16)
__device__ float g_op [MM*DD];
__device__ float g_x  [MM*DD];
__device__ float g_f  [MM*DD];
__device__ float g_proj[BB*EE];
__device__ int   g_lastE[BB*NN*NN];
__device__ float g_bqkv[768];
// fp16 activations (A operands)
__device__ __half g_a[MM*DD];              // nodes / ao / x (sequential reuse)
__device__ __half g_h[MM*DFF];             // FFN hidden
// fp16 transposed weights [N,K] K-major (B operands, single precision)
__device__ __half g_wqkvT[768*DD];
__device__ __half g_woT [DD*DD];
__device__ __half g_w1T [DFF*DD];
__device__ __half g_w2T [DD*DFF];

// ==================== helpers ====================
__device__ __forceinline__ uint32_t smem_u32(const void* p) {
    uint32_t a;
    asm("{ .reg .u64 t; cvta.to.shared.u64 t, %1; cvt.u32.u64 %0, t; }" : "=r"(a) : "l"(p));
    return a;
}
__device__ __forceinline__ void cpa16(uint32_t dst, const void* src) {
    asm volatile("cp.async.cg.shared.global [%0], [%1], 16;" :: "r"(dst), "l"(src));
}
#define CP_COMMIT asm volatile("cp.async.commit_group;" ::: "memory")
#define CP_WAIT2  asm volatile("cp.async.wait_group 2;" ::: "memory")
#define CP_WAIT1  asm volatile("cp.async.wait_group 1;" ::: "memory")
#define CP_WAIT0  asm volatile("cp.async.wait_group 0;" ::: "memory")

// ==================== combined init_lastE + conv(nodes->fp16) ====================
__global__ void prep_kernel(const float* __restrict__ nodes, __half* __restrict__ a) {
    int cid = blockIdx.x;
    if (cid < 8192) {
        size_t idx = (size_t)cid * blockDim.x + threadIdx.x;
        reinterpret_cast<int4*>(g_lastE)[idx] = make_int4(-1, -1, -1, -1);
    } else {
        int i = (cid - 8192) * 256 + threadIdx.x;
        float4 v = reinterpret_cast<const float4*>(nodes)[i];
        __half hh[4] = {__float2half(v.x), __float2half(v.y),
                        __float2half(v.z), __float2half(v.w)};
        reinterpret_cast<uint2*>(a)[i] = *reinterpret_cast<uint2*>(hh);
    }
}

// edge bias projection + adjacency scatter (fused)
__global__ void edge_kernel(const float* __restrict__ ea,
                            const float* __restrict__ ew,
                            const float* __restrict__ ebv,
                            const int* __restrict__ eidx) {
    int idx = blockIdx.x * blockDim.x + threadIdx.x;
    if (idx >= BB * EE) return;
    const float4* p = reinterpret_cast<const float4*>(ea + (size_t)idx * 16);
    const float4* w = reinterpret_cast<const float4*>(ew);
    float s = ebv[0];
    #pragma unroll
    for (int t = 0; t < 4; t++) {
        float4 a = p[t], b = w[t];
        s += a.x * b.x + a.y * b.y + a.z * b.z + a.w * b.w;
    }
    g_proj[idx] = s;
    int b = idx >> 15, e = idx & (EE - 1);
    int si = eidx[(b * 2 + 0) * EE + e];
    int di = eidx[(b * 2 + 1) * EE + e];
    if ((unsigned)si < (unsigned)NN && (unsigned)di < (unsigned)NN)
        atomicMax(&g_lastE[((size_t)(b * NN + si)) * NN + di], e);
}

// all six weight transposes -> fp16 + bias concat; block (32,8)
__global__ void trans_all_kernel(const float* Wq, const float* Wk, const float* Wv,
                                 const float* Wo, const float* W1, const float* W2,
                                 const float* bq, const float* bk, const float* bv) {
    int cid = blockIdx.x;
    if (cid >= 768) {
        int t = (cid - 768) * 256 + threadIdx.y * 32 + threadIdx.x;
        g_bqkv[t] = (t < 256) ? bq[t] : (t < 512 ? bk[t - 256] : bv[t - 512]);
        return;
    }
    __shared__ float t[32][33];
    const float* W; __half* Th; int Nd, ldT, tk, tn;
    if (cid < 192) {
        int m = cid / 64, tt = cid % 64;
        W = (m == 0) ? Wq : (m == 1 ? Wk : Wv);
        Th = g_wqkvT + (size_t)m * 256 * DD;
        Nd = 256; ldT = DD; tk = tt >> 3; tn = tt & 7;
    } else if (cid < 256) {
        int tt = cid - 192;
        W = Wo; Th = g_woT;
        Nd = 256; ldT = DD; tk = tt >> 3; tn = tt & 7;
    } else if (cid < 512) {
        int tt = cid - 256;
        W = W1; Th = g_w1T;
        Nd = 1024; ldT = DD; tk = tt >> 5; tn = tt & 31;
    } else {
        int tt = cid - 512;
        W = W2; Th = g_w2T;
        Nd = 256; ldT = DFF; tk = tt >> 3; tn = tt & 7;
    }
    int k0 = tk * 32, n0 = tn * 32;
    int tx = threadIdx.x, ty = threadIdx.y;
    #pragma unroll
    for (int i = 0; i < 32; i += 8)
        t[ty + i][tx] = W[(size_t)(k0 + ty + i) * Nd + n0 + tx];
    __syncthreads();
    #pragma unroll
    for (int i = 0; i < 32; i += 8)
        Th[(size_t)(n0 + ty + i) * ldT + k0 + tx] = __float2half(t[tx][ty + i]);
}

// ==================== 3-stage cp.async pipelined fp16 single-pass wmma GEMM ====================
// C[M,N] = A[M,K] @ T^T;  A, T fp16 (both rounded; 11-bit mantissa ≈ tf32 accuracy).
// mode 0: Cf = out+bias (fp32); mode 1: Ch = fp16(gelu(out+bias)); mode 2: Ch = fp16(out+bias)
template<int NT>
__global__ void __launch_bounds__(256, 2)
gemm_tc(const __half* __restrict__ A, const __half* __restrict__ Bt,
        const float* __restrict__ bias, float* __restrict__ Cf,
        __half* __restrict__ Ch,
        int M, int N, int K, int mode) {
    extern __shared__ char smem[];
    const int tid = threadIdx.x, wid = tid >> 5;
    constexpr int MW = (NT == 128) ? 4 : 2;
    const int wr = (NT == 128) ? (wid & 1) * 64 : (wid & 3) * 32;
    const int wc = (NT == 128) ? (wid >> 1) * 32 : (wid >> 2) * 32;
    const int m0 = blockIdx.y * 128, n0 = blockIdx.x * NT;
    const int NC = K >> 5;

    constexpr int AH = 0;
    constexpr int BH = 128 * 80;
    constexpr int SS = (128 + NT) * 80;
    const uint32_t sb0 = smem_u32(smem);

    wmma::fragment<wmma::accumulator, 16, 16, 16, float> acc[MW][2];
    #pragma unroll
    for (int i = 0; i < MW; i++)
        #pragma unroll
        for (int j = 0; j < 2; j++) wmma::fill_fragment(acc[i][j], 0.0f);

    const int seg = tid & 3, r = tid >> 2;           // r in 0..63, seg 16B segments

    auto issue = [&](int c, int s) {
        const uint32_t sb = sb0 + s * SS;
        const size_t ka = (size_t)(m0 + r) * K + (c << 5) + seg * 8;
        cpa16(sb + AH + r * 80 + seg * 16,        A + ka);
        cpa16(sb + AH + (r + 64) * 80 + seg * 16, A + ka + (size_t)64 * K);
        const size_t kb = (size_t)(n0 + r) * K + (c << 5) + seg * 8;
        cpa16(sb + BH + r * 80 + seg * 16, Bt + kb);
        if (NT == 128)
            cpa16(sb + BH + (r + 64) * 80 + seg * 16, Bt + kb + (size_t)64 * K);
    };

    issue(0, 0); CP_COMMIT;
    if (NC > 1) { issue(1, 1); CP_COMMIT; }
    int st = 0;
    for (int c = 0; c < NC; c++) {
        if (c + 2 < NC) { issue(c + 2, (c + 2) % 3); CP_COMMIT; CP_WAIT2; }
        else if (c + 1 < NC) { CP_WAIT1; }
        else { CP_WAIT0; }
        __syncthreads();
        const char* base = smem + st * SS;
        st = (st == 2) ? 0 : st + 1;
        const __half* pA = reinterpret_cast<const __half*>(base + AH);
        const __half* pB = reinterpret_cast<const __half*>(base + BH);
        #pragma unroll
        for (int ks = 0; ks < 32; ks += 16) {
            wmma::fragment<wmma::matrix_a, 16, 16, 16, __half, wmma::row_major> a[MW];
            #pragma unroll
            for (int i = 0; i < MW; i++)
                wmma::load_matrix_sync(a[i], pA + (wr + i * 16) * 40 + ks, 40);
            #pragma unroll
            for (int j = 0; j < 2; j++) {
                wmma::fragment<wmma::matrix_b, 16, 16, 16, __half, wmma::col_major> b;
                wmma::load_matrix_sync(b, pB + (wc + j * 16) * 40 + ks, 40);
                #pragma unroll
                for (int i = 0; i < MW; i++)
                    wmma::mma_sync(acc[i][j], a[i], b, acc[i][j]);
            }
        }
        __syncthreads();
    }

    // ---- epilogue via smem ----
    constexpr int LDC = NT + 4;
    float* cs = reinterpret_cast<float*>(smem);
    #pragma unroll
    for (int i = 0; i < MW; i++)
        #pragma unroll
        for (int j = 0; j < 2; j++)
            wmma::store_matrix_sync(&cs[(wr + i * 16) * LDC + wc + j * 16],
                                    acc[i][j], LDC, wmma::mem_row_major);
    __syncthreads();

    constexpr int NIT = (128 * NT / 4) / 256;
    #pragma unroll
    for (int it = 0; it < NIT; it++) {
        int flat = tid + 256 * it;
        int rr = flat / (NT / 4), c4 = flat % (NT / 4);
        const float* src = &cs[rr * LDC + c4 * 4];
        float vals[4];
        #pragma unroll
        for (int q = 0; q < 4; q++) vals[q] = src[q] + bias[n0 + c4 * 4 + q];
        if (mode == 0) {
            *reinterpret_cast<float4*>(&Cf[(size_t)(m0 + rr) * N + n0 + c4 * 4]) =
                *reinterpret_cast<float4*>(vals);
        } else {
            __half hh[4];
            #pragma unroll
            for (int q = 0; q < 4; q++) {
                float v = vals[q];
                if (mode == 1) v = 0.5f * v * (1.0f + erff(v * 0.70710678118654752f));
                hh[q] = __float2half(v);
            }
            size_t o = ((size_t)(m0 + rr) * N + n0 + c4 * 4) >> 2;
            reinterpret_cast<uint2*>(Ch)[o] = *reinterpret_cast<uint2*>(hh);
        }
    }
}

// ==================== sparse masked attention (fp16 qkv, emits fp16 ao) ====================
__global__ void attn_kernel(const float* __restrict__ boxes,
                            const float* __restrict__ geo_w,
                            const float* __restrict__ geo_b,
                            __half* __restrict__ ao) {
    int b = blockIdx.x >> 10;
    int i = blockIdx.x & (NN - 1);
    int tid = threadIdx.x;
    int l = tid & 31, w = tid >> 5;

    __shared__ float sq[DD];
    __shared__ int   sj[NN];
    __shared__ float sv[NN];
    __shared__ int   warpBase[8];
    __shared__ int   nvs;
    __shared__ float sbx[4];

    size_t rowq = (size_t)(b * NN + i) * 768;
    sq[tid] = __half2float(g_qkv[rowq + tid]);
    if (tid < 4) sbx[tid] = boxes[(b * NN + i) * 4 + tid];
    if (tid == 0) nvs = 0;
    __syncthreads();

    float gw0 = geo_w[0], gw1 = geo_w[1], gw2 = geo_w[2], gw3 = geo_w[3],
          gw4 = geo_w[4], gw5 = geo_w[5], gw6 = geo_w[6], gb = geo_b[0];
    float x1i = sbx[0], y1i = sbx[1], x2i = sbx[2], y2i = sbx[3];
    float cxi = 0.5f * (x1i + x2i), cyi = 0.5f * (y1i + y2i);
    float wi = fmaxf(x2i - x1i, 1e-6f), hi = fmaxf(y2i - y1i, 1e-6f);
    float ai = wi * hi;

    const int* lrow = &g_lastE[(size_t)(b * NN + i) * NN];

    for (int it = 0; it < NN / 256; it++) {
        int j = it * 256 + tid;
        int le = lrow[j];
        bool val = (le >= 0) || (j == i);
        unsigned m = __ballot_sync(0xffffffffu, val);
        if (l == 0) warpBase[w] = __popc(m);
        __syncthreads();
        if (tid == 0) {
            int s = nvs;
            for (int kk = 0; kk < 8; kk++) { int c = warpBase[kk]; warpBase[kk] = s; s += c; }
            nvs = s;
        }
        __syncthreads();
        if (val) {
            float4 bj = *reinterpret_cast<const float4*>(&boxes[(b * NN + j) * 4]);
            float x1j = bj.x, y1j = bj.y, x2j = bj.z, y2j = bj.w;
            float cxj = 0.5f * (x1j + x2j), cyj = 0.5f * (y1j + y2j);
            float wj = fmaxf(x2j - x1j, 1e-6f), hj = fmaxf(y2j - y1j, 1e-6f);
            float aj = wj * hj;
            float dx = cxi - cxj, dy = cyi - cyj;
            float lw = logf(wi / wj), lh = logf(hi / hj);
            float dist = sqrtf(dx * dx + dy * dy + 1e-6f);
            float ix1 = fmaxf(x1i, x1j), iy1 = fmaxf(y1i, y1j);
            float ix2 = fminf(x2i, x2j), iy2 = fminf(y2i, y2j);
            float iw = fmaxf(ix2 - ix1, 0.f), ih = fmaxf(iy2 - iy1, 0.f);
            float inter = iw * ih;
            float uni = ai + aj - inter + 1e-6f;
            float iou = inter / uni;
            float ar = ai / fmaxf(aj, 1e-6f);
            float biasv = gw0 * dx + gw1 * dy + gw2 * lw + gw3 * lh
                        + gw4 * dist + gw5 * iou + gw6 * ar + gb;
            if (le >= 0) biasv += g_proj[b * EE + le];
            int pos = warpBase[w] + __popc(m & ((1u << l) - 1u));
            sj[pos] = j;
            sv[pos] = biasv;
        }
        __syncthreads();
    }
    int nv = nvs;

    // q·k: one warp per valid entry; half2 coalesced loads
    for (int t = w; t < nv; t += 8) {
        int j = sj[t];
        const __half2* kp = reinterpret_cast<const __half2*>(&g_qkv[(size_t)(b * NN + j) * 768 + 256]);
        float s = 0.f;
        #pragma unroll
        for (int c = 0; c < 4; c++) {
            int p = l + 32 * c;
            float2 kk = __half22float2(kp[p]);
            s += sq[2 * p] * kk.x + sq[2 * p + 1] * kk.y;
        }
        #pragma unroll
        for (int o = 16; o; o >>= 1) s += __shfl_xor_sync(0xffffffffu, s, o);
        if (l == 0) sv[t] = s * 0.0625f + sv[t];
    }
    __syncthreads();

    if (w == 0) {
        float mx = -3.4e38f;
        for (int t = l; t < nv; t += 32) mx = fmaxf(mx, sv[t]);
        #pragma unroll
        for (int o = 16; o; o >>= 1) mx = fmaxf(mx, __shfl_xor_sync(0xffffffffu, mx, o));
        float sm = 0.f;
        for (int t = l; t < nv; t += 32) { float p = expf(sv[t] - mx); sv[t] = p; sm += p; }
        #pragma unroll
        for (int o = 16; o; o >>= 1) sm += __shfl_xor_sync(0xffffffffu, sm, o);
        float inv = 1.0f / sm;
        for (int t = l; t < nv; t += 32) sv[t] *= inv;
    }
    __syncthreads();

    float acc = 0.f;
    for (int t = 0; t < nv; t++)
        acc += sv[t] * __half2float(g_qkv[(size_t)(b * NN + sj[t]) * 768 + 512 + tid]);
    ao[(size_t)(b * NN + i) * DD + tid] = __float2half(acc);
}

// ==================== residual + LayerNorm: one warp per row ====================
__global__ void ln_kernel(const float* __restrict__ a, const float* __restrict__ res,
                          const float* __restrict__ gam, const float* __restrict__ bet,
                          float* __restrict__ out, __half* __restrict__ oh) {
    int w = threadIdx.x >> 5, l = threadIdx.x & 31;
    int row = blockIdx.x * 8 + w;
    size_t base = (size_t)row * DD;

    float v[8], s = 0.f;
    #pragma unroll
    for (int u = 0; u < 8; u++) {
        int d = l + 32 * u;
        v[u] = a[base + d] + res[base + d];
        s += v[u];
    }
    #pragma unroll
    for (int o = 16; o; o >>= 1) s += __shfl_xor_sync(0xffffffffu, s, o);
    float mean = s * (1.0f / DD);

    float q = 0.f;
    #pragma unroll
    for (int u = 0; u < 8; u++) { float c = v[u] - mean; q += c * c; }
    #pragma unroll
    for (int o = 16; o; o >>= 1) q += __shfl_xor_sync(0xffffffffu, q, o);
    float rstd = rsqrtf(q * (1.0f / DD) + 1e-5f);

    #pragma unroll
    for (int u = 0; u < 8; u++) {
        int d = l + 32 * u;
        float o = (v[u] - mean) * rstd * gam[d] + bet[d];
        out[base + d] = o;
        if (oh) oh[base + d] = __float2half(o);
    }
}

// ==================== launch ====================
extern "C" void kernel_launch(void* const* d_in, const int* in_sizes, int n_in,
                              void* d_out, int out_size) {
    const float* nodes     = (const float*)d_in[0];
    const float* boxes     = (const float*)d_in[1];
    const float* edge_attr = (const float*)d_in[2];
    const float* Wq = (const float*)d_in[3];
    const float* bq = (const float*)d_in[4];
    const float* Wk = (const float*)d_in[5];
    const float* bk = (const float*)d_in[6];
    const float* Wv = (const float*)d_in[7];
    const float* bv = (const float*)d_in[8];
    const float* Wo = (const float*)d_in[9];
    const float* bo = (const float*)d_in[10];
    const float* geo_w  = (const float*)d_in[11];
    const float* geo_b  = (const float*)d_in[12];
    const float* edge_w = (const float*)d_in[13];
    const float* edge_b = (const float*)d_in[14];
    const float* ln1_g = (const float*)d_in[15];
    const float* ln1_b = (const float*)d_in[16];
    const float* ln2_g = (const float*)d_in[17];
    const float* ln2_b = (const float*)d_in[18];
    const float* W1  = (const float*)d_in[19];
    const float* b1f = (const float*)d_in[20];
    const float* W2  = (const float*)d_in[21];
    const float* b2f = (const float*)d_in[22];
    const int* edge_index = (const int*)d_in[24];
    float* out = (float*)d_out;

    float *op, *x, *f, *bqkv;
    __half *qkv, *a, *h, *wqT, *woT, *w1T, *w2T;
    cudaGetSymbolAddress((void**)&qkv, g_qkv);
    cudaGetSymbolAddress((void**)&op,  g_op);
    cudaGetSymbolAddress((void**)&x,   g_x);
    cudaGetSymbolAddress((void**)&f,   g_f);
    cudaGetSymbolAddress((void**)&bqkv, g_bqkv);
    cudaGetSymbolAddress((void**)&a,   g_a);
    cudaGetSymbolAddress((void**)&h,   g_h);
    cudaGetSymbolAddress((void**)&wqT, g_wqkvT);
    cudaGetSymbolAddress((void**)&woT, g_woT);
    cudaGetSymbolAddress((void**)&w1T, g_w1T);
    cudaGetSymbolAddress((void**)&w2T, g_w2T);

    // smem = max(3-stage pipeline, epilogue 128*(NT+4)*4)
    constexpr int SMEM128 = 128 * 132 * 4;            // 67584 (> 61440 pipeline)
    constexpr int SMEM64  = 3 * (128 + 64) * 80;      // 46080 (> 34816 epilogue)
    cudaFuncSetAttribute(gemm_tc<128>, cudaFuncAttributeMaxDynamicSharedMemorySize, SMEM128);
    cudaFuncSetAttribute(gemm_tc<64>,  cudaFuncAttributeMaxDynamicSharedMemorySize, SMEM64);

    // launch order: ncu samples launch #4 -> QKV GEMM
    trans_all_kernel<<<771, dim3(32, 8)>>>(Wq, Wk, Wv, Wo, W1, W2, bq, bk, bv);
    prep_kernel<<<8192 + 2048, 256>>>(nodes, a);
    edge_kernel<<<(BB * EE) / 256, 256>>>(edge_attr, edge_w, edge_b, edge_index);

    // QKV fused: [8192,256] @ T[768,256] -> fp16
    gemm_tc<128><<<dim3(768 / 128, MM / 128), 256, SMEM128>>>(
        a, wqT, bqkv, nullptr, qkv, MM, 768, DD, 2);

    attn_kernel<<<BB * NN, 256>>>(boxes, geo_w, geo_b, a);

    // Wo: [8192,256] @ T[256,256] -> fp32
    gemm_tc<64><<<dim3(DD / 64, MM / 128), 256, SMEM64>>>(
        a, woT, bo, op, nullptr, MM, DD, DD, 0);

    ln_kernel<<<MM / 8, 256>>>(op, nodes, ln1_g, ln1_b, x, a);

    // FFN1 + exact GELU -> fp16 h
    gemm_tc<128><<<dim3(DFF / 128, MM / 128), 256, SMEM128>>>(
        a, w1T, b1f, nullptr, h, MM, DFF, DD, 1);

    // FFN2: [8192,1024] @ T[256,1024] -> fp32
    gemm_tc<64><<<dim3(DD / 64, MM / 128), 256, SMEM64>>>(
        h, w2T, b2f, f, nullptr, MM, DD, DFF, 0);

    ln_kernel<<<MM / 8, 256>>>(f, x, ln2_g, ln2_b, out, nullptr);
}